// round 5
// baseline (speedup 1.0000x reference)
#include <cuda_runtime.h>
#include <cuda_bf16.h>
#include <cstdint>
#include <cstddef>

#define N_NODES 100000
#define N_EDGES 1600000
#define D 128
#define BM 128
#define MROWS 100096   // 782*128, padded row count for plane buffers

// ---------------------------------------------------------------------------
// Device-global scratch (allocation-free rules).
// ---------------------------------------------------------------------------
__device__ int g_deg[N_NODES];
__device__ int g_off[N_NODES];
__device__ int g_cur[N_NODES];
__device__ int g_csr[N_EDGES];                    // src per sorted edge
__device__ uint32_t g_a1h[(size_t)MROWS * 64];    // A_eff hi plane (bf16 pairs)
__device__ uint32_t g_a1l[(size_t)MROWS * 64];    // A_eff lo plane
__device__ uint32_t g_hh[(size_t)MROWS * 64];     // h hi plane
__device__ uint32_t g_hl[(size_t)MROWS * 64];     // h lo plane
__device__ __nv_bfloat16 g_wbh[2][D * D];         // W^T hi  [n][k]
__device__ __nv_bfloat16 g_wbl[2][D * D];         // W^T lo  [n][k]

// ---------------------------------------------------------------------------
// Helpers
// ---------------------------------------------------------------------------
__device__ __forceinline__ uint32_t smem_u32(const void* p) {
    uint32_t a;
    asm("{ .reg .u64 t; cvta.to.shared.u64 t, %1; cvt.u32.u64 %0, t; }"
        : "=r"(a) : "l"(p));
    return a;
}
__device__ __forceinline__ uint32_t pack_bf2(float a, float b) {
    uint16_t ua = __bfloat16_as_ushort(__float2bfloat16(a));
    uint16_t ub = __bfloat16_as_ushort(__float2bfloat16(b));
    return (uint32_t)ua | ((uint32_t)ub << 16);
}
__device__ __forceinline__ float bf_res(float v) {
    return v - __bfloat162float(__float2bfloat16(v));
}
__device__ __forceinline__ void ldm4(uint32_t& r0, uint32_t& r1,
                                     uint32_t& r2, uint32_t& r3, uint32_t addr) {
    asm volatile("ldmatrix.sync.aligned.m8n8.x4.shared.b16 {%0,%1,%2,%3}, [%4];"
                 : "=r"(r0), "=r"(r1), "=r"(r2), "=r"(r3) : "r"(addr));
}
__device__ __forceinline__ void mma_bf16(float* c, const uint32_t* a,
                                         const uint32_t* b) {
    asm volatile(
        "mma.sync.aligned.m16n8k16.row.col.f32.bf16.bf16.f32 "
        "{%0,%1,%2,%3}, {%4,%5,%6,%7}, {%8,%9}, {%0,%1,%2,%3};"
        : "+f"(c[0]), "+f"(c[1]), "+f"(c[2]), "+f"(c[3])
        : "r"(a[0]), "r"(a[1]), "r"(a[2]), "r"(a[3]), "r"(b[0]), "r"(b[1]));
}

// ---------------------------------------------------------------------------
// prep: split W into bf16 hi/lo, transposed to [n][k].
// ---------------------------------------------------------------------------
__global__ void prep_w(const float* __restrict__ W1, const float* __restrict__ W2) {
    int idx = blockIdx.x * blockDim.x + threadIdx.x;
    int which = blockIdx.y;
    const float* W = which ? W2 : W1;
    int k = idx >> 7, n = idx & 127;
    float v = __ldg(&W[k * D + n]);
    g_wbh[which][n * D + k] = __float2bfloat16(v);
    g_wbl[which][n * D + k] = __float2bfloat16(bf_res(v));
}

// ---------------------------------------------------------------------------
// CSR build: zero degrees -> histogram -> scan -> fill
// ---------------------------------------------------------------------------
__global__ void zero_deg() {
    int i = blockIdx.x * blockDim.x + threadIdx.x;
    if (i < N_NODES) g_deg[i] = 0;
}
__global__ void hist_kernel(const int* __restrict__ ei) {
    int i = blockIdx.x * blockDim.x + threadIdx.x;
    int stride = gridDim.x * blockDim.x;
    for (int e = i; e < N_EDGES; e += stride)
        atomicAdd(&g_deg[__ldg(&ei[N_EDGES + e])], 1);
}
__global__ void scan_kernel() {
    __shared__ int sums[1024];
    const int C = 98;   // 1024*98 = 100352 >= N_NODES
    int tid = threadIdx.x;
    int start = tid * C;
    int s = 0;
    for (int j = 0; j < C; j++) {
        int idx = start + j;
        if (idx < N_NODES) s += g_deg[idx];
    }
    sums[tid] = s;
    __syncthreads();
    for (int d = 1; d < 1024; d <<= 1) {
        int v = (tid >= d) ? sums[tid - d] : 0;
        __syncthreads();
        sums[tid] += v;
        __syncthreads();
    }
    int run = sums[tid] - s;   // exclusive prefix
    for (int j = 0; j < C; j++) {
        int idx = start + j;
        if (idx < N_NODES) {
            g_off[idx] = run;
            g_cur[idx] = run;
            run += g_deg[idx];
        }
    }
}
__global__ void fill_kernel(const int* __restrict__ ei) {
    int i = blockIdx.x * blockDim.x + threadIdx.x;
    int stride = gridDim.x * blockDim.x;
    for (int e = i; e < N_EDGES; e += stride) {
        int s = __ldg(&ei[e]);
        int d = __ldg(&ei[N_EDGES + e]);
        int p = atomicAdd(&g_cur[d], 1);
        g_csr[p] = s;
    }
}

// ---------------------------------------------------------------------------
// Gather + GIN combine + bf16 split: one warp per node.
//   A_eff[i] = (1+eps)*x[i] + sum_{j in N(i)} x[j]   -> hi/lo bf16 planes
// ---------------------------------------------------------------------------
__global__ void gather_kernel(const float* __restrict__ x,
                              const float* __restrict__ epsp) {
    int gw = (blockIdx.x * blockDim.x + threadIdx.x) >> 5;
    int lane = threadIdx.x & 31;
    if (gw >= N_NODES) return;
    float scale = 1.0f + __ldg(epsp);
    const float4* xb = (const float4*)x;

    float4 v = __ldg(&xb[(size_t)gw * 32 + lane]);
    float4 acc = make_float4(scale * v.x, scale * v.y, scale * v.z, scale * v.w);

    int base = g_off[gw];
    int deg  = g_deg[gw];
    for (int c = 0; c < deg; c += 32) {
        int e = c + lane;
        int s = (e < deg) ? g_csr[base + e] : 0;
        int lim = min(32, deg - c);
        for (int j = 0; j < lim; j++) {
            int sj = __shfl_sync(0xffffffffu, s, j);
            float4 w = __ldg(&xb[(size_t)sj * 32 + lane]);
            acc.x += w.x; acc.y += w.y; acc.z += w.z; acc.w += w.w;
        }
    }
    uint2 hu, lu;
    hu.x = pack_bf2(acc.x, acc.y);
    hu.y = pack_bf2(acc.z, acc.w);
    lu.x = pack_bf2(bf_res(acc.x), bf_res(acc.y));
    lu.y = pack_bf2(bf_res(acc.z), bf_res(acc.w));
    ((uint2*)g_a1h)[(size_t)gw * 32 + lane] = hu;
    ((uint2*)g_a1l)[(size_t)gw * 32 + lane] = lu;
}

// ---------------------------------------------------------------------------
// bf16x3-split tensor-core GEMM over pre-split planes.
//   SPLIT_OUT=1: C = relu(A@W + b) written as bf16 hi/lo planes (-> h)
//   SPLIT_OUT=0: C = A@W + b written fp32 (-> out)
// CTA tile 128x128xK128, 8 warps (4m x 2n), smem pitch 272B (conflict-free).
// ---------------------------------------------------------------------------
#define PL 272
#define SM_AH 1024
#define SM_AL (SM_AH + 128 * PL)
#define SM_BH (SM_AL + 128 * PL)
#define SM_BL (SM_BH + 128 * PL)
#define SMEM_TOT (SM_BL + 128 * PL)

template<bool SPLIT_OUT>
__global__ void __launch_bounds__(256, 1)
gin_gemm(const uint32_t* __restrict__ Ah, const uint32_t* __restrict__ Al,
         const __nv_bfloat16* __restrict__ Bh, const __nv_bfloat16* __restrict__ Bl,
         const float* __restrict__ bias,
         float* __restrict__ Cf, uint32_t* __restrict__ Chh,
         uint32_t* __restrict__ Chl, int n_rows) {
    extern __shared__ char sm[];
    const int tid = threadIdx.x;
    const int row0 = blockIdx.x * BM;

    float* sb_bias = (float*)sm;
    if (tid < 128) sb_bias[tid] = __ldg(&bias[tid]);

    // ---- Stage A planes (pure copy; rows padded to MROWS so no guard) ----
    {
        const uint4* ah4 = (const uint4*)(Ah + (size_t)row0 * 64);
        const uint4* al4 = (const uint4*)(Al + (size_t)row0 * 64);
        #pragma unroll
        for (int i = 0; i < 8; i++) {
            int idx = tid + i * 256;          // 0..2047 uint4s (16B = 8 bf16)
            int row = idx >> 4, c16 = idx & 15;
            *(uint4*)(sm + SM_AH + row * PL + c16 * 16) = __ldg(&ah4[idx]);
            *(uint4*)(sm + SM_AL + row * PL + c16 * 16) = __ldg(&al4[idx]);
        }
    }
    // ---- Stage B planes ----
    {
        #pragma unroll
        for (int i = 0; i < 8; i++) {
            int idx = tid + i * 256;
            int n = idx >> 4, c16 = idx & 15;
            *(uint4*)(sm + SM_BH + n * PL + c16 * 16) = __ldg((const uint4*)Bh + idx);
            *(uint4*)(sm + SM_BL + n * PL + c16 * 16) = __ldg((const uint4*)Bl + idx);
        }
    }
    __syncthreads();

    const int wid = tid >> 5, lane = tid & 31;
    const int wm = wid & 3, wn = wid >> 2;
    const uint32_t sbase = smem_u32(sm);

    const int i8 = lane & 7;
    const int jA_m = ((lane >> 3) & 1) * 8;
    const int jA_k = (lane >> 4) * 8;
    uint32_t aH0 = sbase + SM_AH + (uint32_t)(wm * 32 + jA_m + i8) * PL + jA_k * 2;
    uint32_t aH1 = aH0 + 16 * PL;
    uint32_t aL0 = aH0 + (SM_AL - SM_AH);
    uint32_t aL1 = aL0 + 16 * PL;
    const int jB_k = ((lane >> 3) & 1) * 8;
    const int jB_n = (lane >> 4) * 8;
    uint32_t bH[4], bL[4];
    #pragma unroll
    for (int g = 0; g < 4; g++) {
        uint32_t nrow = (uint32_t)(wn * 64 + g * 16 + jB_n + i8);
        bH[g] = sbase + SM_BH + nrow * PL + jB_k * 2;
        bL[g] = bH[g] + (SM_BL - SM_BH);
    }

    float acc[2][8][4];
    #pragma unroll
    for (int m = 0; m < 2; m++)
        #pragma unroll
        for (int n = 0; n < 8; n++)
            #pragma unroll
            for (int q = 0; q < 4; q++) acc[m][n][q] = 0.f;

    #pragma unroll
    for (int ks = 0; ks < 8; ks++) {
        const uint32_t ko = ks * 32;
        uint32_t ah[2][4], al[2][4], bh[8][2], bl[8][2];
        ldm4(ah[0][0], ah[0][1], ah[0][2], ah[0][3], aH0 + ko);
        ldm4(ah[1][0], ah[1][1], ah[1][2], ah[1][3], aH1 + ko);
        ldm4(al[0][0], al[0][1], al[0][2], al[0][3], aL0 + ko);
        ldm4(al[1][0], al[1][1], al[1][2], al[1][3], aL1 + ko);
        #pragma unroll
        for (int g = 0; g < 4; g++) {
            ldm4(bh[2 * g][0], bh[2 * g][1], bh[2 * g + 1][0], bh[2 * g + 1][1],
                 bH[g] + ko);
            ldm4(bl[2 * g][0], bl[2 * g][1], bl[2 * g + 1][0], bl[2 * g + 1][1],
                 bL[g] + ko);
        }
        #pragma unroll
        for (int n = 0; n < 8; n++) {
            #pragma unroll
            for (int m = 0; m < 2; m++) {
                mma_bf16(acc[m][n], ah[m], bh[n]);
                mma_bf16(acc[m][n], ah[m], bl[n]);
                mma_bf16(acc[m][n], al[m], bh[n]);
            }
        }
    }

    // ---- Epilogue ----
    const int tig = lane & 3, grp = lane >> 2;
    #pragma unroll
    for (int m = 0; m < 2; m++) {
        int r = row0 + wm * 32 + m * 16 + grp;
        #pragma unroll
        for (int n = 0; n < 8; n++) {
            int col = wn * 64 + n * 8 + tig * 2;
            float b0 = sb_bias[col], b1 = sb_bias[col + 1];
            float2 v0 = make_float2(acc[m][n][0] + b0, acc[m][n][1] + b1);
            float2 v1 = make_float2(acc[m][n][2] + b0, acc[m][n][3] + b1);
            if (SPLIT_OUT) {
                v0.x = fmaxf(v0.x, 0.f); v0.y = fmaxf(v0.y, 0.f);
                v1.x = fmaxf(v1.x, 0.f); v1.y = fmaxf(v1.y, 0.f);
                int ci = (col >> 1);
                if (r < n_rows) {
                    Chh[(size_t)r * 64 + ci] = pack_bf2(v0.x, v0.y);
                    Chl[(size_t)r * 64 + ci] = pack_bf2(bf_res(v0.x), bf_res(v0.y));
                }
                if (r + 8 < n_rows) {
                    Chh[(size_t)(r + 8) * 64 + ci] = pack_bf2(v1.x, v1.y);
                    Chl[(size_t)(r + 8) * 64 + ci] = pack_bf2(bf_res(v1.x), bf_res(v1.y));
                }
            } else {
                if (r < n_rows)     *(float2*)(Cf + (size_t)r * D + col) = v0;
                if (r + 8 < n_rows) *(float2*)(Cf + (size_t)(r + 8) * D + col) = v1;
            }
        }
    }
}

// ---------------------------------------------------------------------------
extern "C" void kernel_launch(void* const* d_in, const int* in_sizes, int n_in,
                              void* d_out, int out_size) {
    const float* x   = (const float*)d_in[0];
    const int*   ei  = (const int*)d_in[1];
    const float* eps = (const float*)d_in[2];
    const float* W1  = (const float*)d_in[3];
    const float* b1  = (const float*)d_in[4];
    const float* W2  = (const float*)d_in[5];
    const float* b2  = (const float*)d_in[6];
    float*       out = (float*)d_out;

    uint32_t *a1h, *a1l, *hh, *hl;
    __nv_bfloat16 *wbh, *wbl;
    cudaGetSymbolAddress((void**)&a1h, g_a1h);
    cudaGetSymbolAddress((void**)&a1l, g_a1l);
    cudaGetSymbolAddress((void**)&hh, g_hh);
    cudaGetSymbolAddress((void**)&hl, g_hl);
    cudaGetSymbolAddress((void**)&wbh, g_wbh);
    cudaGetSymbolAddress((void**)&wbl, g_wbl);

    cudaFuncSetAttribute(gin_gemm<true>,
                         cudaFuncAttributeMaxDynamicSharedMemorySize, SMEM_TOT);
    cudaFuncSetAttribute(gin_gemm<false>,
                         cudaFuncAttributeMaxDynamicSharedMemorySize, SMEM_TOT);

    // W split/transpose
    prep_w<<<dim3(64, 2), 256>>>(W1, W2);

    // CSR build
    zero_deg<<<(N_NODES + 255) / 256, 256>>>();
    hist_kernel<<<1024, 256>>>(ei);
    scan_kernel<<<1, 1024>>>();
    fill_kernel<<<1024, 256>>>(ei);

    // A_eff = (1+eps)x + gather  -> bf16 hi/lo planes
    gather_kernel<<<(N_NODES * 32 + 255) / 256, 256>>>(x, eps);

    int nblk = (N_NODES + BM - 1) / BM;   // 782
    // h = relu(A_eff @ W1 + b1)  -> hi/lo planes
    gin_gemm<true><<<nblk, 256, SMEM_TOT>>>(
        a1h, a1l, wbh, wbl, b1, nullptr, hh, hl, N_NODES);
    // out = h @ W2 + b2
    gin_gemm<false><<<nblk, 256, SMEM_TOT>>>(
        hh, hl, wbh + D * D, wbl + D * D, b2, out, nullptr, nullptr, N_NODES);
}

// round 7
// speedup vs baseline: 1.8565x; 1.8565x over previous
#include <cuda_runtime.h>
#include <cuda_bf16.h>
#include <cstdint>
#include <cstddef>

#define N_NODES 100000
#define N_EDGES 1600000
#define D 128
#define BM 128
#define MROWS 100096      // 782*128 padded rows for plane buffers
#define SCAN_BLK 391      // ceil(100000/256)

// ---------------------------------------------------------------------------
// Device-global scratch (allocation-free rules).
// ---------------------------------------------------------------------------
__device__ int g_deg[N_NODES];
__device__ int g_off[N_NODES];
__device__ int g_cur[N_NODES];
__device__ int g_bsum[SCAN_BLK];
__device__ int g_bpre[SCAN_BLK];
__device__ int g_csr[N_EDGES];
__device__ uint32_t g_a1h[(size_t)MROWS * 64];   // A_eff hi plane (bf16 pairs)
__device__ uint32_t g_a1l[(size_t)MROWS * 64];   // A_eff lo plane
__device__ uint32_t g_hh[(size_t)MROWS * 64];    // h hi plane
__device__ uint32_t g_hl[(size_t)MROWS * 64];    // h lo plane
__device__ __nv_bfloat16 g_wbh[2][D * D];        // W^T hi [n][k]
__device__ __nv_bfloat16 g_wbl[2][D * D];        // W^T lo [n][k]

// ---------------------------------------------------------------------------
// Helpers
// ---------------------------------------------------------------------------
__device__ __forceinline__ uint32_t smem_u32(const void* p) {
    uint32_t a;
    asm("{ .reg .u64 t; cvta.to.shared.u64 t, %1; cvt.u32.u64 %0, t; }"
        : "=r"(a) : "l"(p));
    return a;
}
__device__ __forceinline__ uint32_t pack_bf2(float a, float b) {
    uint16_t ua = __bfloat16_as_ushort(__float2bfloat16(a));
    uint16_t ub = __bfloat16_as_ushort(__float2bfloat16(b));
    return (uint32_t)ua | ((uint32_t)ub << 16);
}
__device__ __forceinline__ float bf_res(float v) {
    return v - __bfloat162float(__float2bfloat16(v));
}
__device__ __forceinline__ void ldm4(uint32_t& r0, uint32_t& r1,
                                     uint32_t& r2, uint32_t& r3, uint32_t addr) {
    asm volatile("ldmatrix.sync.aligned.m8n8.x4.shared.b16 {%0,%1,%2,%3}, [%4];"
                 : "=r"(r0), "=r"(r1), "=r"(r2), "=r"(r3) : "r"(addr));
}
__device__ __forceinline__ void mma_bf16(float* c, const uint32_t* a,
                                         const uint32_t* b) {
    asm volatile(
        "mma.sync.aligned.m16n8k16.row.col.f32.bf16.bf16.f32 "
        "{%0,%1,%2,%3}, {%4,%5,%6,%7}, {%8,%9}, {%0,%1,%2,%3};"
        : "+f"(c[0]), "+f"(c[1]), "+f"(c[2]), "+f"(c[3])
        : "r"(a[0]), "r"(a[1]), "r"(a[2]), "r"(a[3]), "r"(b[0]), "r"(b[1]));
}

// ---------------------------------------------------------------------------
// prep: split W into bf16 hi/lo, transposed to [n][k].
// ---------------------------------------------------------------------------
__global__ void prep_w(const float* __restrict__ W1, const float* __restrict__ W2) {
    int idx = blockIdx.x * blockDim.x + threadIdx.x;
    int which = blockIdx.y;
    const float* W = which ? W2 : W1;
    int k = idx >> 7, n = idx & 127;
    float v = __ldg(&W[k * D + n]);
    g_wbh[which][n * D + k] = __float2bfloat16(v);
    g_wbl[which][n * D + k] = __float2bfloat16(bf_res(v));
}

// ---------------------------------------------------------------------------
// CSR build: zero -> hist -> 3-phase parallel scan -> fill
// ---------------------------------------------------------------------------
__global__ void zero_deg() {
    int i = blockIdx.x * blockDim.x + threadIdx.x;
    if (i < N_NODES) g_deg[i] = 0;
}
__global__ void hist_kernel(const int* __restrict__ ei) {
    int i = blockIdx.x * blockDim.x + threadIdx.x;
    int stride = gridDim.x * blockDim.x;
    for (int e = i; e < N_EDGES; e += stride)
        atomicAdd(&g_deg[__ldg(&ei[N_EDGES + e])], 1);
}
__global__ void scan1_kernel() {
    __shared__ int s[256];
    int tid = threadIdx.x;
    int i = blockIdx.x * 256 + tid;
    int v = (i < N_NODES) ? g_deg[i] : 0;
    s[tid] = v;
    __syncthreads();
    #pragma unroll
    for (int d = 1; d < 256; d <<= 1) {
        int t = (tid >= d) ? s[tid - d] : 0;
        __syncthreads();
        s[tid] += t;
        __syncthreads();
    }
    if (i < N_NODES) g_off[i] = s[tid] - v;       // block-local exclusive
    if (tid == 255) g_bsum[blockIdx.x] = s[255];  // block total
}
__global__ void scan2_kernel() {
    __shared__ int s[512];
    int tid = threadIdx.x;
    int v = (tid < SCAN_BLK) ? g_bsum[tid] : 0;
    s[tid] = v;
    __syncthreads();
    #pragma unroll
    for (int d = 1; d < 512; d <<= 1) {
        int t = (tid >= d) ? s[tid - d] : 0;
        __syncthreads();
        s[tid] += t;
        __syncthreads();
    }
    if (tid < SCAN_BLK) g_bpre[tid] = s[tid] - v;  // exclusive block prefix
}
__global__ void scan3_kernel() {
    int i = blockIdx.x * 256 + threadIdx.x;
    if (i < N_NODES) {
        int o = g_off[i] + g_bpre[blockIdx.x];
        g_off[i] = o;
        g_cur[i] = o;
    }
}
__global__ void fill_kernel(const int* __restrict__ ei) {
    int i = blockIdx.x * blockDim.x + threadIdx.x;
    int stride = gridDim.x * blockDim.x;
    for (int e = i; e < N_EDGES; e += stride) {
        int s = __ldg(&ei[e]);
        int d = __ldg(&ei[N_EDGES + e]);
        int p = atomicAdd(&g_cur[d], 1);
        g_csr[p] = s;
    }
}

// ---------------------------------------------------------------------------
// Gather + GIN combine + bf16 split: one warp per node, 4-way MLP unroll.
// ---------------------------------------------------------------------------
__global__ void gather_kernel(const float* __restrict__ x,
                              const float* __restrict__ epsp) {
    int gw = (blockIdx.x * blockDim.x + threadIdx.x) >> 5;
    int lane = threadIdx.x & 31;
    if (gw >= N_NODES) return;
    float scale = 1.0f + __ldg(epsp);
    const float4* xb = (const float4*)x;

    float4 v = __ldg(&xb[(size_t)gw * 32 + lane]);
    float4 a0 = make_float4(scale * v.x, scale * v.y, scale * v.z, scale * v.w);
    float4 a1 = make_float4(0.f, 0.f, 0.f, 0.f);
    float4 a2 = a1, a3 = a1;

    const int base = g_off[gw];
    const int deg  = g_deg[gw];
    int c = 0;
    for (; c + 4 <= deg; c += 4) {
        int s0 = __ldg(&g_csr[base + c + 0]);
        int s1 = __ldg(&g_csr[base + c + 1]);
        int s2 = __ldg(&g_csr[base + c + 2]);
        int s3 = __ldg(&g_csr[base + c + 3]);
        float4 w0 = __ldg(&xb[(size_t)s0 * 32 + lane]);
        float4 w1 = __ldg(&xb[(size_t)s1 * 32 + lane]);
        float4 w2 = __ldg(&xb[(size_t)s2 * 32 + lane]);
        float4 w3 = __ldg(&xb[(size_t)s3 * 32 + lane]);
        a0.x += w0.x; a0.y += w0.y; a0.z += w0.z; a0.w += w0.w;
        a1.x += w1.x; a1.y += w1.y; a1.z += w1.z; a1.w += w1.w;
        a2.x += w2.x; a2.y += w2.y; a2.z += w2.z; a2.w += w2.w;
        a3.x += w3.x; a3.y += w3.y; a3.z += w3.z; a3.w += w3.w;
    }
    for (; c < deg; c++) {
        int s0 = __ldg(&g_csr[base + c]);
        float4 w0 = __ldg(&xb[(size_t)s0 * 32 + lane]);
        a0.x += w0.x; a0.y += w0.y; a0.z += w0.z; a0.w += w0.w;
    }
    float4 acc;
    acc.x = (a0.x + a1.x) + (a2.x + a3.x);
    acc.y = (a0.y + a1.y) + (a2.y + a3.y);
    acc.z = (a0.z + a1.z) + (a2.z + a3.z);
    acc.w = (a0.w + a1.w) + (a2.w + a3.w);

    uint2 hu, lu;
    hu.x = pack_bf2(acc.x, acc.y);
    hu.y = pack_bf2(acc.z, acc.w);
    lu.x = pack_bf2(bf_res(acc.x), bf_res(acc.y));
    lu.y = pack_bf2(bf_res(acc.z), bf_res(acc.w));
    ((uint2*)g_a1h)[(size_t)gw * 32 + lane] = hu;
    ((uint2*)g_a1l)[(size_t)gw * 32 + lane] = lu;
}

// ---------------------------------------------------------------------------
// bf16x3-split tensor-core GEMM over pre-split planes.
// CTA tile 128(M) x 64(N) x 128(K); grid (782, 2); 2 CTAs/SM.
// 8 warps in 4m x 2n: warp tile 32 rows x 32 cols.
//   SPLIT_OUT=1: C = relu(A@W + b) -> bf16 hi/lo planes
//   SPLIT_OUT=0: C = A@W + b -> fp32
// ---------------------------------------------------------------------------
#define PL 272
#define SM_AH 1024
#define SM_AL (SM_AH + 128 * PL)     // 35840
#define SM_BH (SM_AL + 128 * PL)     // 70656
#define SM_BL (SM_BH + 64 * PL)      // 88064
#define SMEM_TOT (SM_BL + 64 * PL)   // 105472

template<bool SPLIT_OUT>
__global__ void __launch_bounds__(256, 2)
gin_gemm(const uint32_t* __restrict__ Ah, const uint32_t* __restrict__ Al,
         const __nv_bfloat16* __restrict__ Bh, const __nv_bfloat16* __restrict__ Bl,
         const float* __restrict__ bias,
         float* __restrict__ Cf, uint32_t* __restrict__ Chh,
         uint32_t* __restrict__ Chl, int n_rows) {
    extern __shared__ char sm[];
    const int tid = threadIdx.x;
    const int row0 = blockIdx.x * BM;
    const int col0 = blockIdx.y * 64;

    float* sb_bias = (float*)sm;
    if (tid < 64) sb_bias[tid] = __ldg(&bias[col0 + tid]);

    // ---- Stage A planes (pure copy; plane rows padded to MROWS) ----
    {
        const uint4* ah4 = (const uint4*)(Ah + (size_t)row0 * 64);
        const uint4* al4 = (const uint4*)(Al + (size_t)row0 * 64);
        #pragma unroll
        for (int i = 0; i < 8; i++) {
            int idx = tid + i * 256;          // 0..2047 uint4s
            int row = idx >> 4, c16 = idx & 15;
            *(uint4*)(sm + SM_AH + row * PL + c16 * 16) = __ldg(&ah4[idx]);
            *(uint4*)(sm + SM_AL + row * PL + c16 * 16) = __ldg(&al4[idx]);
        }
    }
    // ---- Stage B planes (64 rows of this CTA's column half) ----
    {
        const uint4* bh4 = (const uint4*)Bh + (size_t)col0 * 16;
        const uint4* bl4 = (const uint4*)Bl + (size_t)col0 * 16;
        #pragma unroll
        for (int i = 0; i < 4; i++) {
            int idx = tid + i * 256;          // 0..1023 uint4s
            int n = idx >> 4, c16 = idx & 15;
            *(uint4*)(sm + SM_BH + n * PL + c16 * 16) = __ldg(&bh4[idx]);
            *(uint4*)(sm + SM_BL + n * PL + c16 * 16) = __ldg(&bl4[idx]);
        }
    }
    __syncthreads();

    const int wid = tid >> 5, lane = tid & 31;
    const int wm = wid & 3, wn = wid >> 2;
    const uint32_t sbase = smem_u32(sm);

    const int i8 = lane & 7;
    const int jA_m = ((lane >> 3) & 1) * 8;
    const int jA_k = (lane >> 4) * 8;
    uint32_t aH0 = sbase + SM_AH + (uint32_t)(wm * 32 + jA_m + i8) * PL + jA_k * 2;
    uint32_t aH1 = aH0 + 16 * PL;
    uint32_t aL0 = aH0 + (SM_AL - SM_AH);
    uint32_t aL1 = aL0 + 16 * PL;
    const int jB_k = ((lane >> 3) & 1) * 8;
    const int jB_n = (lane >> 4) * 8;
    uint32_t bH[2], bL[2];
    #pragma unroll
    for (int g = 0; g < 2; g++) {
        uint32_t nrow = (uint32_t)(wn * 32 + g * 16 + jB_n + i8);
        bH[g] = sbase + SM_BH + nrow * PL + jB_k * 2;
        bL[g] = bH[g] + (SM_BL - SM_BH);
    }

    float acc[2][4][4];
    #pragma unroll
    for (int m = 0; m < 2; m++)
        #pragma unroll
        for (int n = 0; n < 4; n++)
            #pragma unroll
            for (int q = 0; q < 4; q++) acc[m][n][q] = 0.f;

    #pragma unroll
    for (int ks = 0; ks < 8; ks++) {
        const uint32_t ko = ks * 32;
        uint32_t ah[2][4], al[2][4], bh[4][2], bl[4][2];
        ldm4(ah[0][0], ah[0][1], ah[0][2], ah[0][3], aH0 + ko);
        ldm4(ah[1][0], ah[1][1], ah[1][2], ah[1][3], aH1 + ko);
        ldm4(al[0][0], al[0][1], al[0][2], al[0][3], aL0 + ko);
        ldm4(al[1][0], al[1][1], al[1][2], al[1][3], aL1 + ko);
        #pragma unroll
        for (int g = 0; g < 2; g++) {
            ldm4(bh[2 * g][0], bh[2 * g][1], bh[2 * g + 1][0], bh[2 * g + 1][1],
                 bH[g] + ko);
            ldm4(bl[2 * g][0], bl[2 * g][1], bl[2 * g + 1][0], bl[2 * g + 1][1],
                 bL[g] + ko);
        }
        #pragma unroll
        for (int n = 0; n < 4; n++) {
            #pragma unroll
            for (int m = 0; m < 2; m++) {
                mma_bf16(acc[m][n], ah[m], bh[n]);
                mma_bf16(acc[m][n], ah[m], bl[n]);
                mma_bf16(acc[m][n], al[m], bh[n]);
            }
        }
    }

    // ---- Epilogue ----
    const int tig = lane & 3, grp = lane >> 2;
    #pragma unroll
    for (int m = 0; m < 2; m++) {
        int r = row0 + wm * 32 + m * 16 + grp;
        #pragma unroll
        for (int n = 0; n < 4; n++) {
            int cl = wn * 32 + n * 8 + tig * 2;     // local col 0..63
            int cg = col0 + cl;                     // global col
            float b0 = sb_bias[cl], b1 = sb_bias[cl + 1];
            float2 v0 = make_float2(acc[m][n][0] + b0, acc[m][n][1] + b1);
            float2 v1 = make_float2(acc[m][n][2] + b0, acc[m][n][3] + b1);
            if (SPLIT_OUT) {
                v0.x = fmaxf(v0.x, 0.f); v0.y = fmaxf(v0.y, 0.f);
                v1.x = fmaxf(v1.x, 0.f); v1.y = fmaxf(v1.y, 0.f);
                int ci = cg >> 1;
                if (r < n_rows) {
                    Chh[(size_t)r * 64 + ci] = pack_bf2(v0.x, v0.y);
                    Chl[(size_t)r * 64 + ci] = pack_bf2(bf_res(v0.x), bf_res(v0.y));
                }
                if (r + 8 < n_rows) {
                    Chh[(size_t)(r + 8) * 64 + ci] = pack_bf2(v1.x, v1.y);
                    Chl[(size_t)(r + 8) * 64 + ci] = pack_bf2(bf_res(v1.x), bf_res(v1.y));
                }
            } else {
                if (r < n_rows)     *(float2*)(Cf + (size_t)r * D + cg) = v0;
                if (r + 8 < n_rows) *(float2*)(Cf + (size_t)(r + 8) * D + cg) = v1;
            }
        }
    }
}

// ---------------------------------------------------------------------------
extern "C" void kernel_launch(void* const* d_in, const int* in_sizes, int n_in,
                              void* d_out, int out_size) {
    const float* x   = (const float*)d_in[0];
    const int*   ei  = (const int*)d_in[1];
    const float* eps = (const float*)d_in[2];
    const float* W1  = (const float*)d_in[3];
    const float* b1  = (const float*)d_in[4];
    const float* W2  = (const float*)d_in[5];
    const float* b2  = (const float*)d_in[6];
    float*       out = (float*)d_out;

    uint32_t *a1h, *a1l, *hh, *hl;
    __nv_bfloat16 *wbh, *wbl;
    cudaGetSymbolAddress((void**)&a1h, g_a1h);
    cudaGetSymbolAddress((void**)&a1l, g_a1l);
    cudaGetSymbolAddress((void**)&hh, g_hh);
    cudaGetSymbolAddress((void**)&hl, g_hl);
    cudaGetSymbolAddress((void**)&wbh, g_wbh);
    cudaGetSymbolAddress((void**)&wbl, g_wbl);

    cudaFuncSetAttribute(gin_gemm<true>,
                         cudaFuncAttributeMaxDynamicSharedMemorySize, SMEM_TOT);
    cudaFuncSetAttribute(gin_gemm<false>,
                         cudaFuncAttributeMaxDynamicSharedMemorySize, SMEM_TOT);

    // W split/transpose
    prep_w<<<dim3(64, 2), 256>>>(W1, W2);

    // CSR build (parallel scan)
    zero_deg<<<(N_NODES + 255) / 256, 256>>>();
    hist_kernel<<<1024, 256>>>(ei);
    scan1_kernel<<<SCAN_BLK, 256>>>();
    scan2_kernel<<<1, 512>>>();
    scan3_kernel<<<SCAN_BLK, 256>>>();
    fill_kernel<<<1024, 256>>>(ei);

    // A_eff = (1+eps)x + gather  -> bf16 hi/lo planes
    gather_kernel<<<(N_NODES * 32 + 255) / 256, 256>>>(x, eps);

    int nblk = (N_NODES + BM - 1) / BM;   // 782
    dim3 grid(nblk, 2);
    // h = relu(A_eff @ W1 + b1)  -> hi/lo planes
    gin_gemm<true><<<grid, 256, SMEM_TOT>>>(
        a1h, a1l, wbh, wbl, b1, nullptr, hh, hl, N_NODES);
    // out = h @ W2 + b2
    gin_gemm<false><<<grid, 256, SMEM_TOT>>>(
        hh, hl, wbh + D * D, wbl + D * D, b2, out, nullptr, nullptr, N_NODES);
}

// round 9
// speedup vs baseline: 2.0497x; 1.1041x over previous
#include <cuda_runtime.h>
#include <cuda_bf16.h>
#include <cstdint>
#include <cstddef>

#define N_NODES 100000
#define N_EDGES 1600000
#define D 128
#define BM 128
#define MROWS 100096      // 782*128 padded rows for plane buffers
#define NTILES 782
#define NPCTA 152         // persistent CTAs (GB300: 152 SMs)

// ---------------------------------------------------------------------------
// Device-global scratch (allocation-free rules; zero-initialized).
// ---------------------------------------------------------------------------
__device__ float g_agg[(size_t)N_NODES * D];
__device__ uint32_t g_a1h[(size_t)MROWS * 64];   // A_eff hi plane (bf16 pairs)
__device__ uint32_t g_a1l[(size_t)MROWS * 64];   // A_eff lo plane
__device__ uint32_t g_hh[(size_t)MROWS * 64];    // h hi plane
__device__ uint32_t g_hl[(size_t)MROWS * 64];    // h lo plane
__device__ __nv_bfloat16 g_wbh[2][D * D];        // W^T hi [n][k]
__device__ __nv_bfloat16 g_wbl[2][D * D];        // W^T lo [n][k]

// ---------------------------------------------------------------------------
// Helpers
// ---------------------------------------------------------------------------
__device__ __forceinline__ uint32_t smem_u32(const void* p) {
    uint32_t a;
    asm("{ .reg .u64 t; cvta.to.shared.u64 t, %1; cvt.u32.u64 %0, t; }"
        : "=r"(a) : "l"(p));
    return a;
}
__device__ __forceinline__ uint32_t pack_bf2(float a, float b) {
    uint16_t ua = __bfloat16_as_ushort(__float2bfloat16(a));
    uint16_t ub = __bfloat16_as_ushort(__float2bfloat16(b));
    return (uint32_t)ua | ((uint32_t)ub << 16);
}
__device__ __forceinline__ float bf_res(float v) {
    return v - __bfloat162float(__float2bfloat16(v));
}
__device__ __forceinline__ void ldm4(uint32_t& r0, uint32_t& r1,
                                     uint32_t& r2, uint32_t& r3, uint32_t addr) {
    asm volatile("ldmatrix.sync.aligned.m8n8.x4.shared.b16 {%0,%1,%2,%3}, [%4];"
                 : "=r"(r0), "=r"(r1), "=r"(r2), "=r"(r3) : "r"(addr));
}
__device__ __forceinline__ void mma_bf16(float* c, const uint32_t* a,
                                         const uint32_t* b) {
    asm volatile(
        "mma.sync.aligned.m16n8k16.row.col.f32.bf16.bf16.f32 "
        "{%0,%1,%2,%3}, {%4,%5,%6,%7}, {%8,%9}, {%0,%1,%2,%3};"
        : "+f"(c[0]), "+f"(c[1]), "+f"(c[2]), "+f"(c[3])
        : "r"(a[0]), "r"(a[1]), "r"(a[2]), "r"(a[3]), "r"(b[0]), "r"(b[1]));
}
__device__ __forceinline__ void cpa16(uint32_t dst, const void* src) {
    asm volatile("cp.async.cg.shared.global [%0], [%1], 16;"
                 :: "r"(dst), "l"(src));
}
#define CP_COMMIT() asm volatile("cp.async.commit_group;" ::: "memory")
#define CP_WAIT1()  asm volatile("cp.async.wait_group 1;" ::: "memory")
#define CP_WAIT0()  asm volatile("cp.async.wait_group 0;" ::: "memory")

// ---------------------------------------------------------------------------
// prep: split W into bf16 hi/lo, transposed to [n][k].
// ---------------------------------------------------------------------------
__global__ void prep_w(const float* __restrict__ W1, const float* __restrict__ W2) {
    int idx = blockIdx.x * blockDim.x + threadIdx.x;
    int which = blockIdx.y;
    const float* W = which ? W2 : W1;
    int k = idx >> 7, n = idx & 127;
    float v = __ldg(&W[k * D + n]);
    g_wbh[which][n * D + k] = __float2bfloat16(v);
    g_wbl[which][n * D + k] = __float2bfloat16(bf_res(v));
}

// ---------------------------------------------------------------------------
// zero + atomic scatter (R4-proven path).
// ---------------------------------------------------------------------------
__global__ void zero_kernel(float4* __restrict__ p, int n4) {
    int i = blockIdx.x * blockDim.x + threadIdx.x;
    if (i < n4) p[i] = make_float4(0.f, 0.f, 0.f, 0.f);
}
__global__ void scatter_kernel(const float* __restrict__ x,
                               const int* __restrict__ ei,
                               float* __restrict__ agg) {
    int gwarp = (blockIdx.x * blockDim.x + threadIdx.x) >> 5;
    int lane = threadIdx.x & 31;
    int nwarp = (gridDim.x * blockDim.x) >> 5;
    for (int e = gwarp; e < N_EDGES; e += nwarp) {
        int s = __ldg(&ei[e]);
        int d = __ldg(&ei[N_EDGES + e]);
        float4 v = __ldg((const float4*)(x + (size_t)s * D) + lane);
        float* dst = agg + (size_t)d * D + lane * 4;
        asm volatile("red.global.add.v4.f32 [%0], {%1, %2, %3, %4};"
                     :: "l"(dst), "f"(v.x), "f"(v.y), "f"(v.z), "f"(v.w)
                     : "memory");
    }
}

// ---------------------------------------------------------------------------
// combine: A_eff = (1+eps)*x + agg -> bf16 hi/lo planes (elementwise).
// ---------------------------------------------------------------------------
__global__ void combine_kernel(const float* __restrict__ x,
                               const float* __restrict__ agg,
                               const float* __restrict__ epsp) {
    int i = blockIdx.x * blockDim.x + threadIdx.x;   // float4 index
    if (i >= N_NODES * 32) return;
    float scale = 1.0f + __ldg(epsp);
    float4 v = __ldg((const float4*)x + i);
    float4 a = __ldg((const float4*)agg + i);
    a.x = fmaf(scale, v.x, a.x);
    a.y = fmaf(scale, v.y, a.y);
    a.z = fmaf(scale, v.z, a.z);
    a.w = fmaf(scale, v.w, a.w);
    uint2 hu, lu;
    hu.x = pack_bf2(a.x, a.y);
    hu.y = pack_bf2(a.z, a.w);
    lu.x = pack_bf2(bf_res(a.x), bf_res(a.y));
    lu.y = pack_bf2(bf_res(a.z), bf_res(a.w));
    ((uint2*)g_a1h)[i] = hu;
    ((uint2*)g_a1l)[i] = lu;
}

// ---------------------------------------------------------------------------
// Persistent double-buffered bf16x3 tensor-core GEMM.
// 152 CTAs, each loops over row-tiles (stride gridDim). B planes + bias staged
// once; A planes (hi/lo) prefetched per tile via cp.async while computing the
// previous tile. CTA tile 128x128xK128, 8 warps (4m x 2n).
//   SPLIT_OUT=1: C = relu(A@W + b) -> bf16 hi/lo planes
//   SPLIT_OUT=0: C = A@W + b -> fp32
// ---------------------------------------------------------------------------
#define PL 272
#define SM_BH 1024
#define SM_BL (SM_BH + 128 * PL)          // 35840
#define SM_A0 (SM_BL + 128 * PL)          // 70656
#define A_PLANE (128 * PL)                // 34816
#define STAGE (2 * A_PLANE)               // 69632 (AH then AL)
#define SMEM_TOT (SM_A0 + 2 * STAGE)      // 209920

template<bool SPLIT_OUT>
__global__ void __launch_bounds__(256, 1)
gin_gemm_persist(const uint32_t* __restrict__ Ah, const uint32_t* __restrict__ Al,
                 const __nv_bfloat16* __restrict__ Bh,
                 const __nv_bfloat16* __restrict__ Bl,
                 const float* __restrict__ bias,
                 float* __restrict__ Cf, uint32_t* __restrict__ Chh,
                 uint32_t* __restrict__ Chl, int n_rows) {
    extern __shared__ char sm[];
    const int tid = threadIdx.x;
    const uint32_t sbase = smem_u32(sm);

    // ---- Stage B planes + bias (once per CTA) ----
    float* sb_bias = (float*)sm;
    if (tid < 128) sb_bias[tid] = __ldg(&bias[tid]);
    {
        #pragma unroll
        for (int i = 0; i < 8; i++) {
            int idx = tid + i * 256;          // 0..2047 uint4s
            int n = idx >> 4, c16 = idx & 15;
            *(uint4*)(sm + SM_BH + n * PL + c16 * 16) = __ldg((const uint4*)Bh + idx);
            *(uint4*)(sm + SM_BL + n * PL + c16 * 16) = __ldg((const uint4*)Bl + idx);
        }
    }

    // ---- ldmatrix lane addressing (stage-relative for A, absolute for B) ----
    const int wid = tid >> 5, lane = tid & 31;
    const int wm = wid & 3, wn = wid >> 2;
    const int i8 = lane & 7;
    const int jA_m = ((lane >> 3) & 1) * 8;
    const int jA_k = (lane >> 4) * 8;
    const uint32_t aoff = (uint32_t)(wm * 32 + jA_m + i8) * PL + jA_k * 2;
    const int jB_k = ((lane >> 3) & 1) * 8;
    const int jB_n = (lane >> 4) * 8;
    uint32_t bH[4], bL[4];
    #pragma unroll
    for (int g = 0; g < 4; g++) {
        uint32_t nrow = (uint32_t)(wn * 64 + g * 16 + jB_n + i8);
        bH[g] = sbase + SM_BH + nrow * PL + jB_k * 2;
        bL[g] = bH[g] + (SM_BL - SM_BH);
    }

    // ---- Prefetch helper: copy A hi/lo planes for a row-tile into a stage ----
    auto prefetch = [&](int tile, int stage) {
        const uint4* ah4 = (const uint4*)(Ah + (size_t)tile * BM * 64);
        const uint4* al4 = (const uint4*)(Al + (size_t)tile * BM * 64);
        uint32_t dst = sbase + SM_A0 + stage * STAGE;
        #pragma unroll
        for (int i = 0; i < 8; i++) {
            int idx = tid + i * 256;
            int row = idx >> 4, c16 = idx & 15;
            uint32_t o = (uint32_t)(row * PL + c16 * 16);
            cpa16(dst + o, &ah4[idx]);
            cpa16(dst + A_PLANE + o, &al4[idx]);
        }
    };

    int t = blockIdx.x;
    if (t < NTILES) {
        prefetch(t, 0);
        CP_COMMIT();
    }
    int stage = 0;
    for (; t < NTILES; t += gridDim.x) {
        int tn = t + gridDim.x;
        if (tn < NTILES) {
            prefetch(tn, stage ^ 1);
            CP_COMMIT();
            CP_WAIT1();
        } else {
            CP_WAIT0();
        }
        __syncthreads();

        const uint32_t abase = sbase + SM_A0 + stage * STAGE;
        uint32_t aH0 = abase + aoff;
        uint32_t aH1 = aH0 + 16 * PL;
        uint32_t aL0 = aH0 + A_PLANE;
        uint32_t aL1 = aL0 + 16 * PL;

        float acc[2][8][4];
        #pragma unroll
        for (int m = 0; m < 2; m++)
            #pragma unroll
            for (int n = 0; n < 8; n++)
                #pragma unroll
                for (int q = 0; q < 4; q++) acc[m][n][q] = 0.f;

        #pragma unroll
        for (int ks = 0; ks < 8; ks++) {
            const uint32_t ko = ks * 32;
            uint32_t ah[2][4], al[2][4], bh[8][2], bl[8][2];
            ldm4(ah[0][0], ah[0][1], ah[0][2], ah[0][3], aH0 + ko);
            ldm4(ah[1][0], ah[1][1], ah[1][2], ah[1][3], aH1 + ko);
            ldm4(al[0][0], al[0][1], al[0][2], al[0][3], aL0 + ko);
            ldm4(al[1][0], al[1][1], al[1][2], al[1][3], aL1 + ko);
            #pragma unroll
            for (int g = 0; g < 4; g++) {
                ldm4(bh[2 * g][0], bh[2 * g][1], bh[2 * g + 1][0], bh[2 * g + 1][1],
                     bH[g] + ko);
                ldm4(bl[2 * g][0], bl[2 * g][1], bl[2 * g + 1][0], bl[2 * g + 1][1],
                     bL[g] + ko);
            }
            #pragma unroll
            for (int n = 0; n < 8; n++) {
                #pragma unroll
                for (int m = 0; m < 2; m++) {
                    mma_bf16(acc[m][n], ah[m], bh[n]);
                    mma_bf16(acc[m][n], ah[m], bl[n]);
                    mma_bf16(acc[m][n], al[m], bh[n]);
                }
            }
        }

        // ---- Epilogue ----
        const int row0 = t * BM;
        const int tig = lane & 3, grp = lane >> 2;
        #pragma unroll
        for (int m = 0; m < 2; m++) {
            int r = row0 + wm * 32 + m * 16 + grp;
            #pragma unroll
            for (int n = 0; n < 8; n++) {
                int col = wn * 64 + n * 8 + tig * 2;
                float b0 = sb_bias[col], b1 = sb_bias[col + 1];
                float2 v0 = make_float2(acc[m][n][0] + b0, acc[m][n][1] + b1);
                float2 v1 = make_float2(acc[m][n][2] + b0, acc[m][n][3] + b1);
                if (SPLIT_OUT) {
                    v0.x = fmaxf(v0.x, 0.f); v0.y = fmaxf(v0.y, 0.f);
                    v1.x = fmaxf(v1.x, 0.f); v1.y = fmaxf(v1.y, 0.f);
                    int ci = col >> 1;
                    if (r < n_rows) {
                        Chh[(size_t)r * 64 + ci] = pack_bf2(v0.x, v0.y);
                        Chl[(size_t)r * 64 + ci] = pack_bf2(bf_res(v0.x), bf_res(v0.y));
                    }
                    if (r + 8 < n_rows) {
                        Chh[(size_t)(r + 8) * 64 + ci] = pack_bf2(v1.x, v1.y);
                        Chl[(size_t)(r + 8) * 64 + ci] = pack_bf2(bf_res(v1.x), bf_res(v1.y));
                    }
                } else {
                    if (r < n_rows)     *(float2*)(Cf + (size_t)r * D + col) = v0;
                    if (r + 8 < n_rows) *(float2*)(Cf + (size_t)(r + 8) * D + col) = v1;
                }
            }
        }
        __syncthreads();   // protect stage buffer before next prefetch overwrites
        stage ^= 1;
    }
}

// ---------------------------------------------------------------------------
extern "C" void kernel_launch(void* const* d_in, const int* in_sizes, int n_in,
                              void* d_out, int out_size) {
    const float* x   = (const float*)d_in[0];
    const int*   ei  = (const int*)d_in[1];
    const float* eps = (const float*)d_in[2];
    const float* W1  = (const float*)d_in[3];
    const float* b1  = (const float*)d_in[4];
    const float* W2  = (const float*)d_in[5];
    const float* b2  = (const float*)d_in[6];
    float*       out = (float*)d_out;

    float* agg;
    uint32_t *a1h, *a1l, *hh, *hl;
    __nv_bfloat16 *wbh, *wbl;
    cudaGetSymbolAddress((void**)&agg, g_agg);
    cudaGetSymbolAddress((void**)&a1h, g_a1h);
    cudaGetSymbolAddress((void**)&a1l, g_a1l);
    cudaGetSymbolAddress((void**)&hh, g_hh);
    cudaGetSymbolAddress((void**)&hl, g_hl);
    cudaGetSymbolAddress((void**)&wbh, g_wbh);
    cudaGetSymbolAddress((void**)&wbl, g_wbl);

    cudaFuncSetAttribute(gin_gemm_persist<true>,
                         cudaFuncAttributeMaxDynamicSharedMemorySize, SMEM_TOT);
    cudaFuncSetAttribute(gin_gemm_persist<false>,
                         cudaFuncAttributeMaxDynamicSharedMemorySize, SMEM_TOT);

    // W split/transpose
    prep_w<<<dim3(64, 2), 256>>>(W1, W2);

    // agg = 0 ; agg[dst] += x[src]
    int n4 = N_NODES * D / 4;
    zero_kernel<<<(n4 + 255) / 256, 256>>>((float4*)agg, n4);
    scatter_kernel<<<2048, 256>>>(x, ei, agg);

    // A_eff planes
    combine_kernel<<<(N_NODES * 32 + 255) / 256, 256>>>(x, agg, eps);

    // h = relu(A_eff @ W1 + b1) -> planes ; out = h @ W2 + b2
    gin_gemm_persist<true><<<NPCTA, 256, SMEM_TOT>>>(
        a1h, a1l, wbh, wbl, b1, nullptr, hh, hl, N_NODES);
    gin_gemm_persist<false><<<NPCTA, 256, SMEM_TOT>>>(
        hh, hl, wbh + D * D, wbl + D * D, b2, out, nullptr, nullptr, N_NODES);
}

// round 10
// speedup vs baseline: 2.1518x; 1.0498x over previous
#include <cuda_runtime.h>
#include <cuda_bf16.h>
#include <cstdint>
#include <cstddef>

#define N_NODES 100000
#define N_EDGES 1600000
#define D 128
#define BM 128
#define MROWS 100096      // 782*128 padded rows for plane buffers
#define NTILES 782
#define NPCTA 152         // persistent CTAs (GB300: 152 SMs)

// ---------------------------------------------------------------------------
// Device-global scratch (allocation-free rules; zero-initialized at load).
// ---------------------------------------------------------------------------
__device__ float g_agg[(size_t)N_NODES * D];
__device__ uint32_t g_a1h[(size_t)MROWS * 64];   // A_eff hi plane (bf16 pairs)
__device__ uint32_t g_a1l[(size_t)MROWS * 64];   // A_eff lo plane
__device__ __nv_bfloat16 g_wbh[2][D * D];        // W^T hi [n][k]
__device__ __nv_bfloat16 g_wbl[2][D * D];        // W^T lo [n][k]

// ---------------------------------------------------------------------------
// Helpers
// ---------------------------------------------------------------------------
__device__ __forceinline__ uint32_t smem_u32(const void* p) {
    uint32_t a;
    asm("{ .reg .u64 t; cvta.to.shared.u64 t, %1; cvt.u32.u64 %0, t; }"
        : "=r"(a) : "l"(p));
    return a;
}
__device__ __forceinline__ uint32_t pack_bf2(float a, float b) {
    uint16_t ua = __bfloat16_as_ushort(__float2bfloat16(a));
    uint16_t ub = __bfloat16_as_ushort(__float2bfloat16(b));
    return (uint32_t)ua | ((uint32_t)ub << 16);
}
__device__ __forceinline__ float bf_res(float v) {
    return v - __bfloat162float(__float2bfloat16(v));
}
__device__ __forceinline__ void ldm4(uint32_t& r0, uint32_t& r1,
                                     uint32_t& r2, uint32_t& r3, uint32_t addr) {
    asm volatile("ldmatrix.sync.aligned.m8n8.x4.shared.b16 {%0,%1,%2,%3}, [%4];"
                 : "=r"(r0), "=r"(r1), "=r"(r2), "=r"(r3) : "r"(addr));
}
__device__ __forceinline__ void mma_bf16(float* c, const uint32_t* a,
                                         const uint32_t* b) {
    asm volatile(
        "mma.sync.aligned.m16n8k16.row.col.f32.bf16.bf16.f32 "
        "{%0,%1,%2,%3}, {%4,%5,%6,%7}, {%8,%9}, {%0,%1,%2,%3};"
        : "+f"(c[0]), "+f"(c[1]), "+f"(c[2]), "+f"(c[3])
        : "r"(a[0]), "r"(a[1]), "r"(a[2]), "r"(a[3]), "r"(b[0]), "r"(b[1]));
}
__device__ __forceinline__ void cpa16(uint32_t dst, const void* src) {
    asm volatile("cp.async.cg.shared.global [%0], [%1], 16;"
                 :: "r"(dst), "l"(src));
}
#define CP_COMMIT() asm volatile("cp.async.commit_group;" ::: "memory")
#define CP_WAIT0()  asm volatile("cp.async.wait_group 0;" ::: "memory")

// ---------------------------------------------------------------------------
// prep: split W into bf16 hi/lo, transposed to [n][k].
// ---------------------------------------------------------------------------
__global__ void prep_w(const float* __restrict__ W1, const float* __restrict__ W2) {
    int idx = blockIdx.x * blockDim.x + threadIdx.x;
    int which = blockIdx.y;
    const float* W = which ? W2 : W1;
    int k = idx >> 7, n = idx & 127;
    float v = __ldg(&W[k * D + n]);
    g_wbh[which][n * D + k] = __float2bfloat16(v);
    g_wbl[which][n * D + k] = __float2bfloat16(bf_res(v));
}

// ---------------------------------------------------------------------------
// init: agg = (1+eps)*x  (replaces the zero pass; same write cost).
// ---------------------------------------------------------------------------
__global__ void init_kernel(const float* __restrict__ x,
                            const float* __restrict__ epsp,
                            float* __restrict__ agg) {
    int i = blockIdx.x * blockDim.x + threadIdx.x;   // float4 index
    if (i >= N_NODES * 32) return;
    float scale = 1.0f + __ldg(epsp);
    float4 v = __ldg((const float4*)x + i);
    v.x *= scale; v.y *= scale; v.z *= scale; v.w *= scale;
    ((float4*)agg)[i] = v;
}

// ---------------------------------------------------------------------------
// scatter: agg[dst] += x[src]  (warp per edge, vector reduction).
// ---------------------------------------------------------------------------
__global__ void scatter_kernel(const float* __restrict__ x,
                               const int* __restrict__ ei,
                               float* __restrict__ agg) {
    int gwarp = (blockIdx.x * blockDim.x + threadIdx.x) >> 5;
    int lane = threadIdx.x & 31;
    int nwarp = (gridDim.x * blockDim.x) >> 5;
    for (int e = gwarp; e < N_EDGES; e += nwarp) {
        int s = __ldg(&ei[e]);
        int d = __ldg(&ei[N_EDGES + e]);
        float4 v = __ldg((const float4*)(x + (size_t)s * D) + lane);
        float* dst = agg + (size_t)d * D + lane * 4;
        asm volatile("red.global.add.v4.f32 [%0], {%1, %2, %3, %4};"
                     :: "l"(dst), "f"(v.x), "f"(v.y), "f"(v.z), "f"(v.w)
                     : "memory");
    }
}

// ---------------------------------------------------------------------------
// split: A_eff planes from agg (pure convert; agg already holds combine).
// ---------------------------------------------------------------------------
__global__ void split_kernel(const float* __restrict__ agg) {
    int i = blockIdx.x * blockDim.x + threadIdx.x;   // float4 index
    if (i >= N_NODES * 32) return;
    float4 a = __ldg((const float4*)agg + i);
    uint2 hu, lu;
    hu.x = pack_bf2(a.x, a.y);
    hu.y = pack_bf2(a.z, a.w);
    lu.x = pack_bf2(bf_res(a.x), bf_res(a.y));
    lu.y = pack_bf2(bf_res(a.z), bf_res(a.w));
    ((uint2*)g_a1h)[i] = hu;
    ((uint2*)g_a1l)[i] = lu;
}

// ---------------------------------------------------------------------------
// Fused persistent 2-layer MLP GEMM (bf16x3 split, tensor cores).
// One CTA/SM; W1/W2 planes + biases staged once. Per row-tile:
//   cp.async A planes -> smem; GEMM1 (3-term); +b1, relu;
//   write h planes back into the SAME smem stage (conflict-free);
//   GEMM2 (3-term) from smem; +b2 -> fp32 out.
// ---------------------------------------------------------------------------
#define PL 272
#define WPLANE (128 * PL)                  // 34816
#define SM_W1H 1024
#define SM_W1L (SM_W1H + WPLANE)
#define SM_W2H (SM_W1L + WPLANE)
#define SM_W2L (SM_W2H + WPLANE)
#define SM_A   (SM_W2L + WPLANE)           // A/h stage: hi plane then lo plane
#define SMEM_TOT (SM_A + 2 * WPLANE)       // 209920

__global__ void __launch_bounds__(256, 1)
gin_mlp_persist(const uint32_t* __restrict__ Ah, const uint32_t* __restrict__ Al,
                const __nv_bfloat16* __restrict__ W1h,
                const __nv_bfloat16* __restrict__ W1l,
                const __nv_bfloat16* __restrict__ W2h,
                const __nv_bfloat16* __restrict__ W2l,
                const float* __restrict__ b1, const float* __restrict__ b2,
                float* __restrict__ out, int n_rows) {
    extern __shared__ char sm[];
    const int tid = threadIdx.x;
    const uint32_t sbase = smem_u32(sm);

    // ---- Stage biases + 4 W planes (once per CTA) ----
    float* sb_b1 = (float*)sm;
    float* sb_b2 = (float*)(sm + 512);
    if (tid < 128) {
        sb_b1[tid] = __ldg(&b1[tid]);
        sb_b2[tid] = __ldg(&b2[tid]);
    }
    {
        const uint4* srcs[4] = {(const uint4*)W1h, (const uint4*)W1l,
                                (const uint4*)W2h, (const uint4*)W2l};
        char* dsts[4] = {sm + SM_W1H, sm + SM_W1L, sm + SM_W2H, sm + SM_W2L};
        #pragma unroll
        for (int p = 0; p < 4; p++) {
            #pragma unroll
            for (int i = 0; i < 8; i++) {
                int idx = tid + i * 256;          // 0..2047 uint4s
                int n = idx >> 4, c16 = idx & 15;
                *(uint4*)(dsts[p] + n * PL + c16 * 16) = __ldg(&srcs[p][idx]);
            }
        }
    }

    // ---- ldmatrix lane addressing ----
    const int wid = tid >> 5, lane = tid & 31;
    const int wm = wid & 3, wn = wid >> 2;
    const int i8 = lane & 7;
    const int jA_m = ((lane >> 3) & 1) * 8;
    const int jA_k = (lane >> 4) * 8;
    const uint32_t aoff = (uint32_t)(wm * 32 + jA_m + i8) * PL + jA_k * 2;
    const uint32_t aH0 = sbase + SM_A + aoff;
    const uint32_t aH1 = aH0 + 16 * PL;
    const uint32_t aL0 = aH0 + WPLANE;
    const uint32_t aL1 = aL0 + 16 * PL;
    const int jB_k = ((lane >> 3) & 1) * 8;
    const int jB_n = (lane >> 4) * 8;
    uint32_t bW[4];   // W1h-relative; other planes at fixed offsets
    #pragma unroll
    for (int g = 0; g < 4; g++) {
        uint32_t nrow = (uint32_t)(wn * 64 + g * 16 + jB_n + i8);
        bW[g] = sbase + SM_W1H + nrow * PL + jB_k * 2;
    }
    const int tig = lane & 3, grp = lane >> 2;

    // 3-term GEMM over the A/h stage with W planes at (bhi_off, blo_off).
    auto gemm3 = [&](uint32_t bhi_off, uint32_t blo_off, float acc[2][8][4]) {
        #pragma unroll
        for (int m = 0; m < 2; m++)
            #pragma unroll
            for (int n = 0; n < 8; n++)
                #pragma unroll
                for (int q = 0; q < 4; q++) acc[m][n][q] = 0.f;
        #pragma unroll
        for (int ks = 0; ks < 8; ks++) {
            const uint32_t ko = ks * 32;
            uint32_t ah[2][4], al[2][4], bh[8][2], bl[8][2];
            ldm4(ah[0][0], ah[0][1], ah[0][2], ah[0][3], aH0 + ko);
            ldm4(ah[1][0], ah[1][1], ah[1][2], ah[1][3], aH1 + ko);
            ldm4(al[0][0], al[0][1], al[0][2], al[0][3], aL0 + ko);
            ldm4(al[1][0], al[1][1], al[1][2], al[1][3], aL1 + ko);
            #pragma unroll
            for (int g = 0; g < 4; g++) {
                ldm4(bh[2 * g][0], bh[2 * g][1], bh[2 * g + 1][0],
                     bh[2 * g + 1][1], bW[g] + bhi_off + ko);
                ldm4(bl[2 * g][0], bl[2 * g][1], bl[2 * g + 1][0],
                     bl[2 * g + 1][1], bW[g] + blo_off + ko);
            }
            #pragma unroll
            for (int n = 0; n < 8; n++) {
                #pragma unroll
                for (int m = 0; m < 2; m++) {
                    mma_bf16(acc[m][n], ah[m], bh[n]);
                    mma_bf16(acc[m][n], ah[m], bl[n]);
                    mma_bf16(acc[m][n], al[m], bh[n]);
                }
            }
        }
    };

    for (int t = blockIdx.x; t < NTILES; t += gridDim.x) {
        // ---- Load A planes for this tile ----
        {
            const uint4* ah4 = (const uint4*)(Ah + (size_t)t * BM * 64);
            const uint4* al4 = (const uint4*)(Al + (size_t)t * BM * 64);
            uint32_t dst = sbase + SM_A;
            #pragma unroll
            for (int i = 0; i < 8; i++) {
                int idx = tid + i * 256;
                int row = idx >> 4, c16 = idx & 15;
                uint32_t o = (uint32_t)(row * PL + c16 * 16);
                cpa16(dst + o, &ah4[idx]);
                cpa16(dst + WPLANE + o, &al4[idx]);
            }
            CP_COMMIT();
            CP_WAIT0();
        }
        __syncthreads();

        // ---- GEMM1: h = relu(A@W1 + b1) ----
        float acc[2][8][4];
        gemm3(0, (uint32_t)(SM_W1L - SM_W1H), acc);
        __syncthreads();   // done reading A planes

        // ---- Write h planes into the A stage (conflict-free) ----
        #pragma unroll
        for (int m = 0; m < 2; m++) {
            int rl = wm * 32 + m * 16 + grp;     // rows rl, rl+8
            #pragma unroll
            for (int n = 0; n < 8; n++) {
                int col = wn * 64 + n * 8 + tig * 2;
                float v0 = fmaxf(acc[m][n][0] + sb_b1[col], 0.f);
                float v1 = fmaxf(acc[m][n][1] + sb_b1[col + 1], 0.f);
                float v2 = fmaxf(acc[m][n][2] + sb_b1[col], 0.f);
                float v3 = fmaxf(acc[m][n][3] + sb_b1[col + 1], 0.f);
                char* hi0 = sm + SM_A + rl * PL + col * 2;
                *(uint32_t*)hi0 = pack_bf2(v0, v1);
                *(uint32_t*)(hi0 + WPLANE) = pack_bf2(bf_res(v0), bf_res(v1));
                char* hi1 = hi0 + 8 * PL;
                *(uint32_t*)hi1 = pack_bf2(v2, v3);
                *(uint32_t*)(hi1 + WPLANE) = pack_bf2(bf_res(v2), bf_res(v3));
            }
        }
        __syncthreads();

        // ---- GEMM2: out = h@W2 + b2 ----
        gemm3((uint32_t)(SM_W2H - SM_W1H), (uint32_t)(SM_W2L - SM_W1H), acc);

        const int row0 = t * BM;
        #pragma unroll
        for (int m = 0; m < 2; m++) {
            int r = row0 + wm * 32 + m * 16 + grp;
            #pragma unroll
            for (int n = 0; n < 8; n++) {
                int col = wn * 64 + n * 8 + tig * 2;
                float b0 = sb_b2[col], b1v = sb_b2[col + 1];
                if (r < n_rows)
                    *(float2*)(out + (size_t)r * D + col) =
                        make_float2(acc[m][n][0] + b0, acc[m][n][1] + b1v);
                if (r + 8 < n_rows)
                    *(float2*)(out + (size_t)(r + 8) * D + col) =
                        make_float2(acc[m][n][2] + b0, acc[m][n][3] + b1v);
            }
        }
        __syncthreads();   // protect A/h stage before next tile's cp.async
    }
}

// ---------------------------------------------------------------------------
extern "C" void kernel_launch(void* const* d_in, const int* in_sizes, int n_in,
                              void* d_out, int out_size) {
    const float* x   = (const float*)d_in[0];
    const int*   ei  = (const int*)d_in[1];
    const float* eps = (const float*)d_in[2];
    const float* W1  = (const float*)d_in[3];
    const float* b1  = (const float*)d_in[4];
    const float* W2  = (const float*)d_in[5];
    const float* b2  = (const float*)d_in[6];
    float*       out = (float*)d_out;

    float* agg;
    uint32_t *a1h, *a1l;
    __nv_bfloat16 *wbh, *wbl;
    cudaGetSymbolAddress((void**)&agg, g_agg);
    cudaGetSymbolAddress((void**)&a1h, g_a1h);
    cudaGetSymbolAddress((void**)&a1l, g_a1l);
    cudaGetSymbolAddress((void**)&wbh, g_wbh);
    cudaGetSymbolAddress((void**)&wbl, g_wbl);

    cudaFuncSetAttribute(gin_mlp_persist,
                         cudaFuncAttributeMaxDynamicSharedMemorySize, SMEM_TOT);

    // W split/transpose
    prep_w<<<dim3(64, 2), 256>>>(W1, W2);

    // agg = (1+eps)x ; agg[dst] += x[src] ; planes = split(agg)
    int nv4 = N_NODES * 32;
    init_kernel<<<(nv4 + 255) / 256, 256>>>(x, eps, agg);
    scatter_kernel<<<2048, 256>>>(x, ei, agg);
    split_kernel<<<(nv4 + 255) / 256, 256>>>(agg);

    // out = (relu(A_eff @ W1 + b1)) @ W2 + b2   — single fused persistent pass
    gin_mlp_persist<<<NPCTA, 256, SMEM_TOT>>>(
        a1h, a1l, wbh, wbl, wbh + D * D, wbl + D * D, b1, b2, out, N_NODES);
}

// round 14
// speedup vs baseline: 2.2272x; 1.0350x over previous
#include <cuda_runtime.h>
#include <cuda_bf16.h>
#include <cstdint>
#include <cstddef>

#define N_NODES 100000
#define N_EDGES 1600000
#define D 128
#define BM 128
#define MROWS 100096      // 782*128 padded row count
#define NTILES 782
#define NPCTA 152         // persistent CTAs (GB300: 152 SMs)

// ---------------------------------------------------------------------------
// Device-global scratch (allocation-free rules; padded to MROWS rows).
// ---------------------------------------------------------------------------
__device__ float g_agg[(size_t)MROWS * D];
__device__ __nv_bfloat16 g_wbh[2][D * D];        // W^T hi [n][k]
__device__ __nv_bfloat16 g_wbl[2][D * D];        // W^T lo [n][k]

// ---------------------------------------------------------------------------
// Helpers
// ---------------------------------------------------------------------------
__device__ __forceinline__ uint32_t smem_u32(const void* p) {
    uint32_t a;
    asm("{ .reg .u64 t; cvta.to.shared.u64 t, %1; cvt.u32.u64 %0, t; }"
        : "=r"(a) : "l"(p));
    return a;
}
__device__ __forceinline__ uint32_t pack_bf2(float a, float b) {
    uint16_t ua = __bfloat16_as_ushort(__float2bfloat16(a));
    uint16_t ub = __bfloat16_as_ushort(__float2bfloat16(b));
    return (uint32_t)ua | ((uint32_t)ub << 16);
}
__device__ __forceinline__ float bf_res(float v) {
    return v - __bfloat162float(__float2bfloat16(v));
}
__device__ __forceinline__ void ldm4(uint32_t& r0, uint32_t& r1,
                                     uint32_t& r2, uint32_t& r3, uint32_t addr) {
    asm volatile("ldmatrix.sync.aligned.m8n8.x4.shared.b16 {%0,%1,%2,%3}, [%4];"
                 : "=r"(r0), "=r"(r1), "=r"(r2), "=r"(r3) : "r"(addr));
}
__device__ __forceinline__ void mma_bf16(float* c, const uint32_t* a,
                                         const uint32_t* b) {
    asm volatile(
        "mma.sync.aligned.m16n8k16.row.col.f32.bf16.bf16.f32 "
        "{%0,%1,%2,%3}, {%4,%5,%6,%7}, {%8,%9}, {%0,%1,%2,%3};"
        : "+f"(c[0]), "+f"(c[1]), "+f"(c[2]), "+f"(c[3])
        : "r"(a[0]), "r"(a[1]), "r"(a[2]), "r"(a[3]), "r"(b[0]), "r"(b[1]));
}

// ---------------------------------------------------------------------------
// prep: split W into bf16 hi/lo, transposed to [n][k].
// ---------------------------------------------------------------------------
__global__ void prep_w(const float* __restrict__ W1, const float* __restrict__ W2) {
    int idx = blockIdx.x * blockDim.x + threadIdx.x;
    int which = blockIdx.y;
    const float* W = which ? W2 : W1;
    int k = idx >> 7, n = idx & 127;
    float v = __ldg(&W[k * D + n]);
    g_wbh[which][n * D + k] = __float2bfloat16(v);
    g_wbl[which][n * D + k] = __float2bfloat16(bf_res(v));
}

// ---------------------------------------------------------------------------
// init: agg = (1+eps)*x  (replaces the zero pass; also zeroes pad rows).
// ---------------------------------------------------------------------------
__global__ void init_kernel(const float* __restrict__ x,
                            const float* __restrict__ epsp,
                            float* __restrict__ agg) {
    int i = blockIdx.x * blockDim.x + threadIdx.x;   // float4 index
    if (i >= MROWS * 32) return;
    float4 v = make_float4(0.f, 0.f, 0.f, 0.f);
    if (i < N_NODES * 32) {
        float scale = 1.0f + __ldg(epsp);
        v = __ldg((const float4*)x + i);
        v.x *= scale; v.y *= scale; v.z *= scale; v.w *= scale;
    }
    ((float4*)agg)[i] = v;
}

// ---------------------------------------------------------------------------
// scatter: agg[dst] += x[src]  (warp per edge, vector reduction).
// ---------------------------------------------------------------------------
__global__ void scatter_kernel(const float* __restrict__ x,
                               const int* __restrict__ ei,
                               float* __restrict__ agg) {
    int gwarp = (blockIdx.x * blockDim.x + threadIdx.x) >> 5;
    int lane = threadIdx.x & 31;
    int nwarp = (gridDim.x * blockDim.x) >> 5;
    for (int e = gwarp; e < N_EDGES; e += nwarp) {
        int s = __ldg(&ei[e]);
        int d = __ldg(&ei[N_EDGES + e]);
        float4 v = __ldg((const float4*)(x + (size_t)s * D) + lane);
        float* dst = agg + (size_t)d * D + lane * 4;
        asm volatile("red.global.add.v4.f32 [%0], {%1, %2, %3, %4};"
                     :: "l"(dst), "f"(v.x), "f"(v.y), "f"(v.z), "f"(v.w)
                     : "memory");
    }
}

// ---------------------------------------------------------------------------
// Fused persistent 2-layer MLP GEMM (bf16x3 split, tensor cores).
// One CTA/SM; W1/W2 planes + biases staged once. Per row-tile:
//   LDG fp32 agg tile -> convert -> bf16 hi/lo planes in smem (fused split);
//   GEMM1 (3-term); +b1, relu; h planes written back into the SAME stage;
//   GEMM2 (3-term); +b2 -> fp32 out.
// ---------------------------------------------------------------------------
#define PL 272
#define WPLANE (128 * PL)                  // 34816
#define SM_W1H 1024
#define SM_W1L (SM_W1H + WPLANE)
#define SM_W2H (SM_W1L + WPLANE)
#define SM_W2L (SM_W2H + WPLANE)
#define SM_A   (SM_W2L + WPLANE)           // A/h stage: hi plane then lo plane
#define SMEM_TOT (SM_A + 2 * WPLANE)       // 209920

__global__ void __launch_bounds__(256, 1)
gin_mlp_persist(const float* __restrict__ agg,
                const __nv_bfloat16* __restrict__ W1h,
                const __nv_bfloat16* __restrict__ W1l,
                const __nv_bfloat16* __restrict__ W2h,
                const __nv_bfloat16* __restrict__ W2l,
                const float* __restrict__ b1, const float* __restrict__ b2,
                float* __restrict__ out, int n_rows) {
    extern __shared__ char sm[];
    const int tid = threadIdx.x;
    const uint32_t sbase = smem_u32(sm);

    // ---- Stage biases + 4 W planes (once per CTA) ----
    float* sb_b1 = (float*)sm;
    float* sb_b2 = (float*)(sm + 512);
    if (tid < 128) {
        sb_b1[tid] = __ldg(&b1[tid]);
        sb_b2[tid] = __ldg(&b2[tid]);
    }
    {
        const uint4* srcs[4] = {(const uint4*)W1h, (const uint4*)W1l,
                                (const uint4*)W2h, (const uint4*)W2l};
        char* dsts[4] = {sm + SM_W1H, sm + SM_W1L, sm + SM_W2H, sm + SM_W2L};
        #pragma unroll
        for (int p = 0; p < 4; p++) {
            #pragma unroll
            for (int i = 0; i < 8; i++) {
                int idx = tid + i * 256;          // 0..2047 uint4s
                int n = idx >> 4, c16 = idx & 15;
                *(uint4*)(dsts[p] + n * PL + c16 * 16) = __ldg(&srcs[p][idx]);
            }
        }
    }

    // ---- ldmatrix lane addressing ----
    const int wid = tid >> 5, lane = tid & 31;
    const int wm = wid & 3, wn = wid >> 2;
    const int i8 = lane & 7;
    const int jA_m = ((lane >> 3) & 1) * 8;
    const int jA_k = (lane >> 4) * 8;
    const uint32_t aoff = (uint32_t)(wm * 32 + jA_m + i8) * PL + jA_k * 2;
    const uint32_t aH0 = sbase + SM_A + aoff;
    const uint32_t aH1 = aH0 + 16 * PL;
    const uint32_t aL0 = aH0 + WPLANE;
    const uint32_t aL1 = aL0 + 16 * PL;
    const int jB_k = ((lane >> 3) & 1) * 8;
    const int jB_n = (lane >> 4) * 8;
    uint32_t bW[4];   // W1h-relative; other planes at fixed offsets
    #pragma unroll
    for (int g = 0; g < 4; g++) {
        uint32_t nrow = (uint32_t)(wn * 64 + g * 16 + jB_n + i8);
        bW[g] = sbase + SM_W1H + nrow * PL + jB_k * 2;
    }
    const int tig = lane & 3, grp = lane >> 2;

    // 3-term GEMM over the A/h stage with W planes at (bhi_off, blo_off).
    auto gemm3 = [&](uint32_t bhi_off, uint32_t blo_off, float acc[2][8][4]) {
        #pragma unroll
        for (int m = 0; m < 2; m++)
            #pragma unroll
            for (int n = 0; n < 8; n++)
                #pragma unroll
                for (int q = 0; q < 4; q++) acc[m][n][q] = 0.f;
        #pragma unroll
        for (int ks = 0; ks < 8; ks++) {
            const uint32_t ko = ks * 32;
            uint32_t ah[2][4], al[2][4], bh[8][2], bl[8][2];
            ldm4(ah[0][0], ah[0][1], ah[0][2], ah[0][3], aH0 + ko);
            ldm4(ah[1][0], ah[1][1], ah[1][2], ah[1][3], aH1 + ko);
            ldm4(al[0][0], al[0][1], al[0][2], al[0][3], aL0 + ko);
            ldm4(al[1][0], al[1][1], al[1][2], al[1][3], aL1 + ko);
            #pragma unroll
            for (int g = 0; g < 4; g++) {
                ldm4(bh[2 * g][0], bh[2 * g][1], bh[2 * g + 1][0],
                     bh[2 * g + 1][1], bW[g] + bhi_off + ko);
                ldm4(bl[2 * g][0], bl[2 * g][1], bl[2 * g + 1][0],
                     bl[2 * g + 1][1], bW[g] + blo_off + ko);
            }
            #pragma unroll
            for (int n = 0; n < 8; n++) {
                #pragma unroll
                for (int m = 0; m < 2; m++) {
                    mma_bf16(acc[m][n], ah[m], bh[n]);
                    mma_bf16(acc[m][n], ah[m], bl[n]);
                    mma_bf16(acc[m][n], al[m], bh[n]);
                }
            }
        }
    };

    for (int t = blockIdx.x; t < NTILES; t += gridDim.x) {
        // ---- Fused split: LDG fp32 agg tile -> bf16 hi/lo planes in smem ----
        {
            const float4* a4 = (const float4*)(agg + (size_t)t * BM * D);
            #pragma unroll
            for (int i = 0; i < 16; i++) {
                int idx = tid + i * 256;          // 0..4095 float4s
                int row = idx >> 5, c4 = idx & 31;
                float4 v = __ldg(&a4[idx]);
                uint2 hu, lu;
                hu.x = pack_bf2(v.x, v.y);
                hu.y = pack_bf2(v.z, v.w);
                lu.x = pack_bf2(bf_res(v.x), bf_res(v.y));
                lu.y = pack_bf2(bf_res(v.z), bf_res(v.w));
                char* dst = sm + SM_A + row * PL + c4 * 8;
                *(uint2*)dst = hu;
                *(uint2*)(dst + WPLANE) = lu;
            }
        }
        __syncthreads();

        // ---- GEMM1: h = relu(A@W1 + b1) ----
        float acc[2][8][4];
        gemm3(0, (uint32_t)(SM_W1L - SM_W1H), acc);
        __syncthreads();   // done reading A planes

        // ---- Write h planes into the A stage (conflict-free) ----
        #pragma unroll
        for (int m = 0; m < 2; m++) {
            int rl = wm * 32 + m * 16 + grp;     // rows rl, rl+8
            #pragma unroll
            for (int n = 0; n < 8; n++) {
                int col = wn * 64 + n * 8 + tig * 2;
                float v0 = fmaxf(acc[m][n][0] + sb_b1[col], 0.f);
                float v1 = fmaxf(acc[m][n][1] + sb_b1[col + 1], 0.f);
                float v2 = fmaxf(acc[m][n][2] + sb_b1[col], 0.f);
                float v3 = fmaxf(acc[m][n][3] + sb_b1[col + 1], 0.f);
                char* hi0 = sm + SM_A + rl * PL + col * 2;
                *(uint32_t*)hi0 = pack_bf2(v0, v1);
                *(uint32_t*)(hi0 + WPLANE) = pack_bf2(bf_res(v0), bf_res(v1));
                char* hi1 = hi0 + 8 * PL;
                *(uint32_t*)hi1 = pack_bf2(v2, v3);
                *(uint32_t*)(hi1 + WPLANE) = pack_bf2(bf_res(v2), bf_res(v3));
            }
        }
        __syncthreads();

        // ---- GEMM2: out = h@W2 + b2 ----
        gemm3((uint32_t)(SM_W2H - SM_W1H), (uint32_t)(SM_W2L - SM_W1H), acc);

        const int row0 = t * BM;
        #pragma unroll
        for (int m = 0; m < 2; m++) {
            int r = row0 + wm * 32 + m * 16 + grp;
            #pragma unroll
            for (int n = 0; n < 8; n++) {
                int col = wn * 64 + n * 8 + tig * 2;
                float b0 = sb_b2[col], b1v = sb_b2[col + 1];
                if (r < n_rows)
                    *(float2*)(out + (size_t)r * D + col) =
                        make_float2(acc[m][n][0] + b0, acc[m][n][1] + b1v);
                if (r + 8 < n_rows)
                    *(float2*)(out + (size_t)(r + 8) * D + col) =
                        make_float2(acc[m][n][2] + b0, acc[m][n][3] + b1v);
            }
        }
        __syncthreads();   // protect A/h stage before next tile overwrites
    }
}

// ---------------------------------------------------------------------------
extern "C" void kernel_launch(void* const* d_in, const int* in_sizes, int n_in,
                              void* d_out, int out_size) {
    const float* x   = (const float*)d_in[0];
    const int*   ei  = (const int*)d_in[1];
    const float* eps = (const float*)d_in[2];
    const float* W1  = (const float*)d_in[3];
    const float* b1  = (const float*)d_in[4];
    const float* W2  = (const float*)d_in[5];
    const float* b2  = (const float*)d_in[6];
    float*       out = (float*)d_out;

    float* agg;
    __nv_bfloat16 *wbh, *wbl;
    cudaGetSymbolAddress((void**)&agg, g_agg);
    cudaGetSymbolAddress((void**)&wbh, g_wbh);
    cudaGetSymbolAddress((void**)&wbl, g_wbl);

    cudaFuncSetAttribute(gin_mlp_persist,
                         cudaFuncAttributeMaxDynamicSharedMemorySize, SMEM_TOT);

    // W split/transpose
    prep_w<<<dim3(64, 2), 256>>>(W1, W2);

    // agg = (1+eps)x ; agg[dst] += x[src]
    int nv4 = MROWS * 32;
    init_kernel<<<(nv4 + 255) / 256, 256>>>(x, eps, agg);
    scatter_kernel<<<2048, 256>>>(x, ei, agg);

    // out = (relu(A_eff @ W1 + b1)) @ W2 + b2   — single fused persistent pass
    gin_mlp_persist<<<NPCTA, 256, SMEM_TOT>>>(
        agg, wbh, wbl, wbh + D * D, wbl + D * D, b1, b2, out, N_NODES);
}

// round 16
// speedup vs baseline: 2.7882x; 1.2519x over previous
#include <cuda_runtime.h>
#include <cuda_bf16.h>
#include <cstdint>
#include <cstddef>

#define N_NODES 100000
#define N_EDGES 1600000
#define D 128
#define BM 128
#define MROWS 100096      // 782*128 padded row count
#define NTILES 782
#define NPCTA 152         // persistent CTAs (GB300: 152 SMs)
#define SCAN_BLK 391      // ceil(100000/256)

// ---------------------------------------------------------------------------
// Device-global scratch (allocation-free rules; zero-init at load; pad rows of
// the plane buffers are never written -> stay zero).
// ---------------------------------------------------------------------------
__device__ int g_deg[N_NODES];
__device__ int g_off[N_NODES];
__device__ int g_cur[N_NODES];
__device__ int g_bsum[SCAN_BLK];
__device__ int g_bpre[SCAN_BLK];
__device__ int g_csr[N_EDGES];
__device__ uint32_t g_a1h[(size_t)MROWS * 64];   // A_eff hi plane (bf16 pairs)
__device__ uint32_t g_a1l[(size_t)MROWS * 64];   // A_eff lo plane
__device__ __nv_bfloat16 g_wbh[2][D * D];        // W^T hi [n][k]
__device__ __nv_bfloat16 g_wbl[2][D * D];        // W^T lo [n][k]

// ---------------------------------------------------------------------------
// Helpers
// ---------------------------------------------------------------------------
__device__ __forceinline__ uint32_t smem_u32(const void* p) {
    uint32_t a;
    asm("{ .reg .u64 t; cvta.to.shared.u64 t, %1; cvt.u32.u64 %0, t; }"
        : "=r"(a) : "l"(p));
    return a;
}
__device__ __forceinline__ uint32_t pack_bf2(float a, float b) {
    uint16_t ua = __bfloat16_as_ushort(__float2bfloat16(a));
    uint16_t ub = __bfloat16_as_ushort(__float2bfloat16(b));
    return (uint32_t)ua | ((uint32_t)ub << 16);
}
__device__ __forceinline__ float bf_res(float v) {
    return v - __bfloat162float(__float2bfloat16(v));
}
__device__ __forceinline__ void ldm4(uint32_t& r0, uint32_t& r1,
                                     uint32_t& r2, uint32_t& r3, uint32_t addr) {
    asm volatile("ldmatrix.sync.aligned.m8n8.x4.shared.b16 {%0,%1,%2,%3}, [%4];"
                 : "=r"(r0), "=r"(r1), "=r"(r2), "=r"(r3) : "r"(addr));
}
__device__ __forceinline__ void mma_bf16(float* c, const uint32_t* a,
                                         const uint32_t* b) {
    asm volatile(
        "mma.sync.aligned.m16n8k16.row.col.f32.bf16.bf16.f32 "
        "{%0,%1,%2,%3}, {%4,%5,%6,%7}, {%8,%9}, {%0,%1,%2,%3};"
        : "+f"(c[0]), "+f"(c[1]), "+f"(c[2]), "+f"(c[3])
        : "r"(a[0]), "r"(a[1]), "r"(a[2]), "r"(a[3]), "r"(b[0]), "r"(b[1]));
}
__device__ __forceinline__ void cpa16(uint32_t dst, const void* src) {
    asm volatile("cp.async.cg.shared.global [%0], [%1], 16;"
                 :: "r"(dst), "l"(src));
}
#define CP_COMMIT() asm volatile("cp.async.commit_group;" ::: "memory")
#define CP_WAIT0()  asm volatile("cp.async.wait_group 0;" ::: "memory")

// ---------------------------------------------------------------------------
// prep: split W into bf16 hi/lo, transposed to [n][k].
// ---------------------------------------------------------------------------
__global__ void prep_w(const float* __restrict__ W1, const float* __restrict__ W2) {
    int idx = blockIdx.x * blockDim.x + threadIdx.x;
    int which = blockIdx.y;
    const float* W = which ? W2 : W1;
    int k = idx >> 7, n = idx & 127;
    float v = __ldg(&W[k * D + n]);
    g_wbh[which][n * D + k] = __float2bfloat16(v);
    g_wbl[which][n * D + k] = __float2bfloat16(bf_res(v));
}

// ---------------------------------------------------------------------------
// CSR build: zero -> hist -> 3-phase parallel scan -> fill
// ---------------------------------------------------------------------------
__global__ void zero_deg() {
    int i = blockIdx.x * blockDim.x + threadIdx.x;
    if (i < N_NODES) g_deg[i] = 0;
}
__global__ void hist_kernel(const int* __restrict__ ei) {
    int i = blockIdx.x * blockDim.x + threadIdx.x;
    int stride = gridDim.x * blockDim.x;
    for (int e = i; e < N_EDGES; e += stride)
        atomicAdd(&g_deg[__ldg(&ei[N_EDGES + e])], 1);
}
__global__ void scan1_kernel() {
    __shared__ int s[256];
    int tid = threadIdx.x;
    int i = blockIdx.x * 256 + tid;
    int v = (i < N_NODES) ? g_deg[i] : 0;
    s[tid] = v;
    __syncthreads();
    #pragma unroll
    for (int d = 1; d < 256; d <<= 1) {
        int t = (tid >= d) ? s[tid - d] : 0;
        __syncthreads();
        s[tid] += t;
        __syncthreads();
    }
    if (i < N_NODES) g_off[i] = s[tid] - v;
    if (tid == 255) g_bsum[blockIdx.x] = s[255];
}
__global__ void scan2_kernel() {
    __shared__ int s[512];
    int tid = threadIdx.x;
    int v = (tid < SCAN_BLK) ? g_bsum[tid] : 0;
    s[tid] = v;
    __syncthreads();
    #pragma unroll
    for (int d = 1; d < 512; d <<= 1) {
        int t = (tid >= d) ? s[tid - d] : 0;
        __syncthreads();
        s[tid] += t;
        __syncthreads();
    }
    if (tid < SCAN_BLK) g_bpre[tid] = s[tid] - v;
}
__global__ void scan3_kernel() {
    int i = blockIdx.x * 256 + threadIdx.x;
    if (i < N_NODES) {
        int o = g_off[i] + g_bpre[blockIdx.x];
        g_off[i] = o;
        g_cur[i] = o;
    }
}
__global__ void fill_kernel(const int* __restrict__ ei) {
    int i = blockIdx.x * blockDim.x + threadIdx.x;
    int stride = gridDim.x * blockDim.x;
    for (int e = i; e < N_EDGES; e += stride) {
        int s = __ldg(&ei[e]);
        int d = __ldg(&ei[N_EDGES + e]);
        int p = atomicAdd(&g_cur[d], 1);
        g_csr[p] = s;
    }
}

// ---------------------------------------------------------------------------
// Gather + GIN combine + bf16 split: one warp per node, 4-way MLP unroll.
//   A_eff[i] = (1+eps)*x[i] + sum_{j in N(i)} x[j]  -> hi/lo planes directly.
// ---------------------------------------------------------------------------
__global__ void gather_kernel(const float* __restrict__ x,
                              const float* __restrict__ epsp) {
    int gw = (blockIdx.x * blockDim.x + threadIdx.x) >> 5;
    int lane = threadIdx.x & 31;
    if (gw >= N_NODES) return;
    float scale = 1.0f + __ldg(epsp);
    const float4* xb = (const float4*)x;

    float4 v = __ldg(&xb[(size_t)gw * 32 + lane]);
    float4 a0 = make_float4(scale * v.x, scale * v.y, scale * v.z, scale * v.w);
    float4 a1 = make_float4(0.f, 0.f, 0.f, 0.f);
    float4 a2 = a1, a3 = a1;

    const int base = g_off[gw];
    const int deg  = g_deg[gw];
    int c = 0;
    for (; c + 4 <= deg; c += 4) {
        int s0 = __ldg(&g_csr[base + c + 0]);
        int s1 = __ldg(&g_csr[base + c + 1]);
        int s2 = __ldg(&g_csr[base + c + 2]);
        int s3 = __ldg(&g_csr[base + c + 3]);
        float4 w0 = __ldg(&xb[(size_t)s0 * 32 + lane]);
        float4 w1 = __ldg(&xb[(size_t)s1 * 32 + lane]);
        float4 w2 = __ldg(&xb[(size_t)s2 * 32 + lane]);
        float4 w3 = __ldg(&xb[(size_t)s3 * 32 + lane]);
        a0.x += w0.x; a0.y += w0.y; a0.z += w0.z; a0.w += w0.w;
        a1.x += w1.x; a1.y += w1.y; a1.z += w1.z; a1.w += w1.w;
        a2.x += w2.x; a2.y += w2.y; a2.z += w2.z; a2.w += w2.w;
        a3.x += w3.x; a3.y += w3.y; a3.z += w3.z; a3.w += w3.w;
    }
    for (; c < deg; c++) {
        int s0 = __ldg(&g_csr[base + c]);
        float4 w0 = __ldg(&xb[(size_t)s0 * 32 + lane]);
        a0.x += w0.x; a0.y += w0.y; a0.z += w0.z; a0.w += w0.w;
    }
    float4 acc;
    acc.x = (a0.x + a1.x) + (a2.x + a3.x);
    acc.y = (a0.y + a1.y) + (a2.y + a3.y);
    acc.z = (a0.z + a1.z) + (a2.z + a3.z);
    acc.w = (a0.w + a1.w) + (a2.w + a3.w);

    uint2 hu, lu;
    hu.x = pack_bf2(acc.x, acc.y);
    hu.y = pack_bf2(acc.z, acc.w);
    lu.x = pack_bf2(bf_res(acc.x), bf_res(acc.y));
    lu.y = pack_bf2(bf_res(acc.z), bf_res(acc.w));
    ((uint2*)g_a1h)[(size_t)gw * 32 + lane] = hu;
    ((uint2*)g_a1l)[(size_t)gw * 32 + lane] = lu;
}

// ---------------------------------------------------------------------------
// Fused persistent 2-layer MLP GEMM (bf16x3 split, tensor cores).
// One CTA/SM; W1/W2 planes + biases staged once. Per row-tile:
//   cp.async A hi/lo planes -> smem; GEMM1 (3-term); +b1, relu;
//   h planes written back into the SAME stage; GEMM2 (3-term); +b2 -> fp32.
// ---------------------------------------------------------------------------
#define PL 272
#define WPLANE (128 * PL)                  // 34816
#define SM_W1H 1024
#define SM_W1L (SM_W1H + WPLANE)
#define SM_W2H (SM_W1L + WPLANE)
#define SM_W2L (SM_W2H + WPLANE)
#define SM_A   (SM_W2L + WPLANE)           // A/h stage: hi plane then lo plane
#define SMEM_TOT (SM_A + 2 * WPLANE)       // 209920

__global__ void __launch_bounds__(256, 1)
gin_mlp_persist(const uint32_t* __restrict__ Ah, const uint32_t* __restrict__ Al,
                const __nv_bfloat16* __restrict__ W1h,
                const __nv_bfloat16* __restrict__ W1l,
                const __nv_bfloat16* __restrict__ W2h,
                const __nv_bfloat16* __restrict__ W2l,
                const float* __restrict__ b1, const float* __restrict__ b2,
                float* __restrict__ out, int n_rows) {
    extern __shared__ char sm[];
    const int tid = threadIdx.x;
    const uint32_t sbase = smem_u32(sm);

    // ---- Stage biases + 4 W planes (once per CTA) ----
    float* sb_b1 = (float*)sm;
    float* sb_b2 = (float*)(sm + 512);
    if (tid < 128) {
        sb_b1[tid] = __ldg(&b1[tid]);
        sb_b2[tid] = __ldg(&b2[tid]);
    }
    {
        const uint4* srcs[4] = {(const uint4*)W1h, (const uint4*)W1l,
                                (const uint4*)W2h, (const uint4*)W2l};
        char* dsts[4] = {sm + SM_W1H, sm + SM_W1L, sm + SM_W2H, sm + SM_W2L};
        #pragma unroll
        for (int p = 0; p < 4; p++) {
            #pragma unroll
            for (int i = 0; i < 8; i++) {
                int idx = tid + i * 256;
                int n = idx >> 4, c16 = idx & 15;
                *(uint4*)(dsts[p] + n * PL + c16 * 16) = __ldg(&srcs[p][idx]);
            }
        }
    }

    // ---- ldmatrix lane addressing ----
    const int wid = tid >> 5, lane = tid & 31;
    const int wm = wid & 3, wn = wid >> 2;
    const int i8 = lane & 7;
    const int jA_m = ((lane >> 3) & 1) * 8;
    const int jA_k = (lane >> 4) * 8;
    const uint32_t aoff = (uint32_t)(wm * 32 + jA_m + i8) * PL + jA_k * 2;
    const uint32_t aH0 = sbase + SM_A + aoff;
    const uint32_t aH1 = aH0 + 16 * PL;
    const uint32_t aL0 = aH0 + WPLANE;
    const uint32_t aL1 = aL0 + 16 * PL;
    const int jB_k = ((lane >> 3) & 1) * 8;
    const int jB_n = (lane >> 4) * 8;
    uint32_t bW[4];
    #pragma unroll
    for (int g = 0; g < 4; g++) {
        uint32_t nrow = (uint32_t)(wn * 64 + g * 16 + jB_n + i8);
        bW[g] = sbase + SM_W1H + nrow * PL + jB_k * 2;
    }
    const int tig = lane & 3, grp = lane >> 2;

    auto gemm3 = [&](uint32_t bhi_off, uint32_t blo_off, float acc[2][8][4]) {
        #pragma unroll
        for (int m = 0; m < 2; m++)
            #pragma unroll
            for (int n = 0; n < 8; n++)
                #pragma unroll
                for (int q = 0; q < 4; q++) acc[m][n][q] = 0.f;
        #pragma unroll
        for (int ks = 0; ks < 8; ks++) {
            const uint32_t ko = ks * 32;
            uint32_t ah[2][4], al[2][4], bh[8][2], bl[8][2];
            ldm4(ah[0][0], ah[0][1], ah[0][2], ah[0][3], aH0 + ko);
            ldm4(ah[1][0], ah[1][1], ah[1][2], ah[1][3], aH1 + ko);
            ldm4(al[0][0], al[0][1], al[0][2], al[0][3], aL0 + ko);
            ldm4(al[1][0], al[1][1], al[1][2], al[1][3], aL1 + ko);
            #pragma unroll
            for (int g = 0; g < 4; g++) {
                ldm4(bh[2 * g][0], bh[2 * g][1], bh[2 * g + 1][0],
                     bh[2 * g + 1][1], bW[g] + bhi_off + ko);
                ldm4(bl[2 * g][0], bl[2 * g][1], bl[2 * g + 1][0],
                     bl[2 * g + 1][1], bW[g] + blo_off + ko);
            }
            #pragma unroll
            for (int n = 0; n < 8; n++) {
                #pragma unroll
                for (int m = 0; m < 2; m++) {
                    mma_bf16(acc[m][n], ah[m], bh[n]);
                    mma_bf16(acc[m][n], ah[m], bl[n]);
                    mma_bf16(acc[m][n], al[m], bh[n]);
                }
            }
        }
    };

    for (int t = blockIdx.x; t < NTILES; t += gridDim.x) {
        // ---- Load A hi/lo planes for this tile (pure cp.async copy) ----
        {
            const uint4* ah4 = (const uint4*)(Ah + (size_t)t * BM * 64);
            const uint4* al4 = (const uint4*)(Al + (size_t)t * BM * 64);
            uint32_t dst = sbase + SM_A;
            #pragma unroll
            for (int i = 0; i < 8; i++) {
                int idx = tid + i * 256;
                int row = idx >> 4, c16 = idx & 15;
                uint32_t o = (uint32_t)(row * PL + c16 * 16);
                cpa16(dst + o, &ah4[idx]);
                cpa16(dst + WPLANE + o, &al4[idx]);
            }
            CP_COMMIT();
            CP_WAIT0();
        }
        __syncthreads();

        // ---- GEMM1: h = relu(A@W1 + b1) ----
        float acc[2][8][4];
        gemm3(0, (uint32_t)(SM_W1L - SM_W1H), acc);
        __syncthreads();

        // ---- Write h planes into the A stage (conflict-free) ----
        #pragma unroll
        for (int m = 0; m < 2; m++) {
            int rl = wm * 32 + m * 16 + grp;
            #pragma unroll
            for (int n = 0; n < 8; n++) {
                int col = wn * 64 + n * 8 + tig * 2;
                float v0 = fmaxf(acc[m][n][0] + sb_b1[col], 0.f);
                float v1 = fmaxf(acc[m][n][1] + sb_b1[col + 1], 0.f);
                float v2 = fmaxf(acc[m][n][2] + sb_b1[col], 0.f);
                float v3 = fmaxf(acc[m][n][3] + sb_b1[col + 1], 0.f);
                char* hi0 = sm + SM_A + rl * PL + col * 2;
                *(uint32_t*)hi0 = pack_bf2(v0, v1);
                *(uint32_t*)(hi0 + WPLANE) = pack_bf2(bf_res(v0), bf_res(v1));
                char* hi1 = hi0 + 8 * PL;
                *(uint32_t*)hi1 = pack_bf2(v2, v3);
                *(uint32_t*)(hi1 + WPLANE) = pack_bf2(bf_res(v2), bf_res(v3));
            }
        }
        __syncthreads();

        // ---- GEMM2: out = h@W2 + b2 ----
        gemm3((uint32_t)(SM_W2H - SM_W1H), (uint32_t)(SM_W2L - SM_W1H), acc);

        const int row0 = t * BM;
        #pragma unroll
        for (int m = 0; m < 2; m++) {
            int r = row0 + wm * 32 + m * 16 + grp;
            #pragma unroll
            for (int n = 0; n < 8; n++) {
                int col = wn * 64 + n * 8 + tig * 2;
                float b0 = sb_b2[col], b1v = sb_b2[col + 1];
                if (r < n_rows)
                    *(float2*)(out + (size_t)r * D + col) =
                        make_float2(acc[m][n][0] + b0, acc[m][n][1] + b1v);
                if (r + 8 < n_rows)
                    *(float2*)(out + (size_t)(r + 8) * D + col) =
                        make_float2(acc[m][n][2] + b0, acc[m][n][3] + b1v);
            }
        }
        __syncthreads();
    }
}

// ---------------------------------------------------------------------------
extern "C" void kernel_launch(void* const* d_in, const int* in_sizes, int n_in,
                              void* d_out, int out_size) {
    const float* x   = (const float*)d_in[0];
    const int*   ei  = (const int*)d_in[1];
    const float* eps = (const float*)d_in[2];
    const float* W1  = (const float*)d_in[3];
    const float* b1  = (const float*)d_in[4];
    const float* W2  = (const float*)d_in[5];
    const float* b2  = (const float*)d_in[6];
    float*       out = (float*)d_out;

    uint32_t *a1h, *a1l;
    __nv_bfloat16 *wbh, *wbl;
    cudaGetSymbolAddress((void**)&a1h, g_a1h);
    cudaGetSymbolAddress((void**)&a1l, g_a1l);
    cudaGetSymbolAddress((void**)&wbh, g_wbh);
    cudaGetSymbolAddress((void**)&wbl, g_wbl);

    cudaFuncSetAttribute(gin_mlp_persist,
                         cudaFuncAttributeMaxDynamicSharedMemorySize, SMEM_TOT);

    // W split/transpose
    prep_w<<<dim3(64, 2), 256>>>(W1, W2);

    // CSR build (parallel scan)
    zero_deg<<<(N_NODES + 255) / 256, 256>>>();
    hist_kernel<<<1024, 256>>>(ei);
    scan1_kernel<<<SCAN_BLK, 256>>>();
    scan2_kernel<<<1, 512>>>();
    scan3_kernel<<<SCAN_BLK, 256>>>();
    fill_kernel<<<1024, 256>>>(ei);

    // A_eff = (1+eps)x + gather  -> bf16 hi/lo planes (no atomic-RED stream)
    gather_kernel<<<(N_NODES * 32 + 255) / 256, 256>>>(x, eps);

    // out = (relu(A_eff @ W1 + b1)) @ W2 + b2
    gin_mlp_persist<<<NPCTA, 256, SMEM_TOT>>>(
        a1h, a1l, wbh, wbl, wbh + D * D, wbl + D * D, b1, b2, out, N_NODES);
}